// round 13
// baseline (speedup 1.0000x reference)
#include <cuda_runtime.h>
#include <cuda_fp16.h>
#include <mma.h>
#include <cstdint>

using namespace nvcuda;

#define D_MODEL 1024
#define N_HEADS 16
#define HEAD_DIM 64
#define BB 4
#define TT 2048
#define BT (BB * TT)  // 8192

// ---------------- scratch (__device__ globals; no allocs allowed) ----------
__device__ __half g_Xh[(size_t)BT * D_MODEL];
__device__ __half g_Wh[4][(size_t)D_MODEL * D_MODEL];
__device__ __half g_Chh[(size_t)BT * D_MODEL];
__device__ float g_Q[(size_t)BT * D_MODEL];   // tf32-rounded
__device__ float g_K[(size_t)BT * D_MODEL];   // tf32-rounded
__device__ float g_V[(size_t)BT * D_MODEL];   // tf32-rounded

// ---------------- helpers ---------------------------------------------------
__device__ __forceinline__ uint32_t smem_u32(const void* p) {
    uint32_t a;
    asm("{ .reg .u64 t; cvta.to.shared.u64 t, %1; cvt.u32.u64 %0, t; }"
        : "=r"(a) : "l"(p));
    return a;
}
#define CP_ASYNC16(dst, src) \
    asm volatile("cp.async.cg.shared.global [%0], [%1], 16;" :: "r"(dst), "l"(src) : "memory")
#define CP_ASYNC_COMMIT() asm volatile("cp.async.commit_group;" ::: "memory")
#define CP_ASYNC_WAIT0() asm volatile("cp.async.wait_group 0;" ::: "memory")
#define CP_ASYNC_WAIT1() asm volatile("cp.async.wait_group 1;" ::: "memory")

// ---------------- fp32 -> fp16 pre-converts ---------------------------------
__global__ __launch_bounds__(256) void conv_f2h(const float4* __restrict__ in,
                                                uint2* __restrict__ out, int n4) {
    int i = blockIdx.x * 256 + threadIdx.x;
    if (i < n4) {
        float4 v = in[i];
        __half2 a = __floats2half2_rn(v.x, v.y);
        __half2 b = __floats2half2_rn(v.z, v.w);
        uint2 o;
        o.x = *(uint32_t*)&a;
        o.y = *(uint32_t*)&b;
        out[i] = o;
    }
}

// all four weight matrices in one launch (blockIdx.y selects the matrix)
__global__ __launch_bounds__(256) void conv_w4(const float4* __restrict__ w0,
                                               const float4* __restrict__ w1,
                                               const float4* __restrict__ w2,
                                               const float4* __restrict__ w3,
                                               uint2* __restrict__ outbase, int n4) {
    const float4* in = (blockIdx.y == 0) ? w0 : (blockIdx.y == 1) ? w1
                       : (blockIdx.y == 2) ? w2 : w3;
    uint2* out = outbase + (size_t)blockIdx.y * n4;
    int i = blockIdx.x * 256 + threadIdx.x;
    if (i < n4) {
        float4 v = in[i];
        __half2 a = __floats2half2_rn(v.x, v.y);
        __half2 b = __floats2half2_rn(v.z, v.w);
        uint2 o;
        o.x = *(uint32_t*)&a;
        o.y = *(uint32_t*)&b;
        out[i] = o;
    }
}

// ---------------------------------------------------------------------------
// fp16 WMMA GEMM core (proven R8-R12 datapath).
// OUT_TF32: round output to tf32. else: +bias fp32 out.
// ---------------------------------------------------------------------------
#define BM 128
#define BN 128
#define BK 32
#define A_LDH 40
#define B_LDH 136
#define C_LDF 136
#define A_BYTES (BM * A_LDH * 2)
#define B_BYTES (BK * B_LDH * 2)
#define BUF_BYTES (A_BYTES + B_BYTES)
#define G_SMEM_BYTES (BM * C_LDF * 4)
#define G_NCHUNK (D_MODEL / BK)

template <int OUT_TF32>
__device__ __forceinline__ void gemm_body(const __half* __restrict__ A,
                                          const __half* __restrict__ Bm,
                                          float* __restrict__ C,
                                          const float* __restrict__ bias,
                                          int bm, int bn, float* sm) {
    const int tid = threadIdx.x;
    const int wid = tid >> 5;
    const int warp_m = wid >> 1;
    const int warp_n = wid & 1;
    const uint32_t sbase = smem_u32(sm);

    wmma::fragment<wmma::accumulator, 16, 16, 16, float> acc[2][4];
#pragma unroll
    for (int i = 0; i < 2; ++i)
#pragma unroll
        for (int j = 0; j < 4; ++j) wmma::fill_fragment(acc[i][j], 0.f);

    const __half* Ab = A + (size_t)bm * D_MODEL;
    const __half* Bb = Bm + bn;

    auto issue = [&](int c) {
        const uint32_t buf = sbase + (uint32_t)(c & 1) * BUF_BYTES;
        const __half* Ag = Ab + c * BK;
        const __half* Bg = Bb + (size_t)(c * BK) * D_MODEL;
#pragma unroll
        for (int i = 0; i < 2; ++i) {
            int idx = i * 256 + tid;
            int row = idx >> 2, seg = idx & 3;
            CP_ASYNC16(buf + (uint32_t)(row * A_LDH + seg * 8) * 2,
                       Ag + (size_t)row * D_MODEL + seg * 8);
        }
#pragma unroll
        for (int i = 0; i < 2; ++i) {
            int idx = i * 256 + tid;
            int row = idx >> 4, seg = idx & 15;
            CP_ASYNC16(buf + A_BYTES + (uint32_t)(row * B_LDH + seg * 8) * 2,
                       Bg + (size_t)row * D_MODEL + seg * 8);
        }
        CP_ASYNC_COMMIT();
    };

    issue(0);
    for (int c = 0; c < G_NCHUNK; ++c) {
        if (c + 1 < G_NCHUNK) {
            issue(c + 1);
            CP_ASYNC_WAIT1();
        } else {
            CP_ASYNC_WAIT0();
        }
        __syncthreads();

        const __half* As = (const __half*)((const char*)sm + (size_t)(c & 1) * BUF_BYTES);
        const __half* Bs = As + A_BYTES / 2;

#pragma unroll
        for (int ks = 0; ks < BK / 16; ++ks) {
            wmma::fragment<wmma::matrix_a, 16, 16, 16, __half, wmma::row_major> a[2];
            wmma::fragment<wmma::matrix_b, 16, 16, 16, __half, wmma::row_major> b[4];
#pragma unroll
            for (int i = 0; i < 2; ++i)
                wmma::load_matrix_sync(
                    a[i], As + (size_t)(warp_m * 32 + i * 16) * A_LDH + ks * 16, A_LDH);
#pragma unroll
            for (int j = 0; j < 4; ++j)
                wmma::load_matrix_sync(
                    b[j], Bs + (size_t)(ks * 16) * B_LDH + warp_n * 64 + j * 16, B_LDH);
#pragma unroll
            for (int i = 0; i < 2; ++i)
#pragma unroll
                for (int j = 0; j < 4; ++j)
                    wmma::mma_sync(acc[i][j], a[i], b[j], acc[i][j]);
        }
        __syncthreads();
    }

    float* Cs = sm;
#pragma unroll
    for (int i = 0; i < 2; ++i)
#pragma unroll
        for (int j = 0; j < 4; ++j)
            wmma::store_matrix_sync(
                Cs + (size_t)(warp_m * 32 + i * 16) * C_LDF + warp_n * 64 + j * 16,
                acc[i][j], C_LDF, wmma::mem_row_major);
    __syncthreads();

#pragma unroll
    for (int i = 0; i < 16; ++i) {
        int idx = i * 256 + tid;
        int row = idx >> 5, c4 = (idx & 31) * 4;
        float4 v = *(const float4*)(Cs + (size_t)row * C_LDF + c4);
        if (OUT_TF32) {
            uint4 o;
            asm("cvt.rna.tf32.f32 %0, %1;" : "=r"(o.x) : "f"(v.x));
            asm("cvt.rna.tf32.f32 %0, %1;" : "=r"(o.y) : "f"(v.y));
            asm("cvt.rna.tf32.f32 %0, %1;" : "=r"(o.z) : "f"(v.z));
            asm("cvt.rna.tf32.f32 %0, %1;" : "=r"(o.w) : "f"(v.w));
            *(uint4*)(C + (size_t)(bm + row) * D_MODEL + bn + c4) = o;
        } else {
            v.x += bias[bn + c4 + 0];
            v.y += bias[bn + c4 + 1];
            v.z += bias[bn + c4 + 2];
            v.w += bias[bn + c4 + 3];
            *(float4*)(C + (size_t)(bm + row) * D_MODEL + bn + c4) = v;
        }
    }
}

// fused Q/K/V projection
__global__ __launch_bounds__(256) void gemm_qkv(const __half* __restrict__ A,
                                                const __half* __restrict__ W0,
                                                const __half* __restrict__ W1,
                                                const __half* __restrict__ W2,
                                                float* __restrict__ C0,
                                                float* __restrict__ C1,
                                                float* __restrict__ C2) {
    extern __shared__ float sm[];
    const int which = blockIdx.x >> 3;
    const int bn = (blockIdx.x & 7) * BN;
    const int bm = blockIdx.y * BM;
    const __half* Bm = (which == 0) ? W0 : (which == 1) ? W1 : W2;
    float* C = (which == 0) ? C0 : (which == 1) ? C1 : C2;
    gemm_body<1>(A, Bm, C, nullptr, bm, bn, sm);
}

// O projection (+bias)
__global__ __launch_bounds__(256) void gemm_o(const __half* __restrict__ A,
                                              const __half* __restrict__ Bm,
                                              float* __restrict__ C,
                                              const float* __restrict__ bias) {
    extern __shared__ float sm[];
    gemm_body<0>(A, Bm, C, bias, blockIdx.y * BM, blockIdx.x * BN, sm);
}

// ---------------------------------------------------------------------------
// tf32 WMMA flash attention (causal) — R12 schedule at 256 threads:
// 8 warps x 16-row strips, 128-row q tile, K0/K1+V0/V1 double buffers,
// one combined commit group per tile (issued at tile top), 2 syncs/tile.
// 16 warps/SM at 2 CTAs -> hides fragment-load latency (tensor 51% -> up).
// qt reversed (heavy first). Ls aliased onto K0 (dead at epilogue).
// ---------------------------------------------------------------------------
#define F_LD 68
#define KV_BYTES (64 * F_LD * 4)            // 17408
#define OFF_K0 0
#define OFF_V0 (2 * KV_BYTES)               // 34816 (V0/V1 follow K0/K1)
#define OFF_PB (4 * KV_BYTES)               // 69632 (S/P/O staging, 128 x F_LD)
#define OFF_ONE (OFF_PB + 128 * F_LD * 4)   // 104448 (8x16 ones)
#define F_SMEM_BYTES (OFF_ONE + 512)        // 104960 (102.5KB) -> 2 CTAs/SM

__global__ __launch_bounds__(256) void flash_t(const float* __restrict__ Q,
                                               const float* __restrict__ K,
                                               const float* __restrict__ V,
                                               __half* __restrict__ O) {
    extern __shared__ char smb[];
    float* Ps = (float*)(smb + OFF_PB);
    float* Ones = (float*)(smb + OFF_ONE);
    float* Ls = (float*)(smb + OFF_K0);   // aliased onto K0 (epilogue only)

    const int tid = threadIdx.x;
    const int w = tid >> 5;               // 0..7
    const int l = tid & 31;
    const int qt = (int)(gridDim.y - 1 - blockIdx.y);  // heavy tiles first
    const int bh = blockIdx.x;
    const int b = bh >> 4;
    const int h = bh & 15;

    const size_t headoff = (size_t)h * HEAD_DIM;
    const uint32_t sbase = smem_u32(smb);
    const int sr0 = w * 16;               // warp strip base row (16 rows)

    // ---- stage Q*0.125 (exact scale; stays tf32) + ones ----
    {
        const float* Qg = Q + (size_t)(b * TT + qt * 128) * D_MODEL + headoff;
        for (int idx = tid; idx < 128 * 16; idx += 256) {
            int row = idx >> 4, c4 = (idx & 15) * 4;
            float4 v = *(const float4*)(Qg + (size_t)row * D_MODEL + c4);
            v.x *= 0.125f; v.y *= 0.125f; v.z *= 0.125f; v.w *= 0.125f;
            *(float4*)(Ps + (size_t)row * F_LD + c4) = v;
        }
        if (tid < 128) Ones[tid] = 1.0f;  // 8x16 = 128 floats
    }
    __syncthreads();

    wmma::fragment<wmma::matrix_a, 16, 16, 8, wmma::precision::tf32,
                   wmma::row_major> qa[8];
#pragma unroll
    for (int ks = 0; ks < 8; ++ks)
        wmma::load_matrix_sync(qa[ks], Ps + (size_t)sr0 * F_LD + ks * 8, F_LD);

    wmma::fragment<wmma::matrix_b, 16, 16, 8, wmma::precision::tf32,
                   wmma::row_major> b_ones;
    wmma::load_matrix_sync(b_ones, Ones, 16);

    wmma::fragment<wmma::accumulator, 16, 16, 8, float> oacc[4], lacc;
#pragma unroll
    for (int n = 0; n < 4; ++n) wmma::fill_fragment(oacc[n], 0.f);
    wmma::fill_fragment(lacc, 0.f);

    const float* Kb = K + (size_t)(b * TT) * D_MODEL + headoff;
    const float* Vb = V + (size_t)(b * TT) * D_MODEL + headoff;

    // combined K+V tile load, ONE commit group (256 threads)
    auto issueKV = [&](int t) {
        const uint32_t kbuf = sbase + OFF_K0 + (uint32_t)(t & 1) * KV_BYTES;
        const uint32_t vbuf = sbase + OFF_V0 + (uint32_t)(t & 1) * KV_BYTES;
        const float* Kg = Kb + (size_t)(t * 64) * D_MODEL;
        const float* Vg = Vb + (size_t)(t * 64) * D_MODEL;
#pragma unroll
        for (int i = 0; i < 4; ++i) {
            int idx = i * 256 + tid;
            int row = idx >> 4, c4 = (idx & 15) * 4;
            uint32_t off = (uint32_t)(row * F_LD + c4) * 4;
            CP_ASYNC16(kbuf + off, Kg + (size_t)row * D_MODEL + c4);
            CP_ASYNC16(vbuf + off, Vg + (size_t)row * D_MODEL + c4);
        }
        CP_ASYNC_COMMIT();
    };

    issueKV(0);

    const int nkt = 2 * qt + 2;

    for (int kt = 0; kt < nkt; ++kt) {
        CP_ASYNC_WAIT0();   // only group(kt) pending here
        __syncthreads();    // K(kt), V(kt) visible to all warps

        if (kt + 1 < nkt) issueKV(kt + 1);  // overlaps this whole tile

        // causal role of this warp for this tile (16-row strips)
        const bool skip = (kt == 2 * qt + 1) && (w < 4);
        const bool mask = ((kt == 2 * qt) && (w < 4)) ||
                          ((kt == 2 * qt + 1) && (w >= 4));

        const float* Ks = (const float*)(smb + OFF_K0 + (size_t)(kt & 1) * KV_BYTES);
        const float* Vs = (const float*)(smb + OFF_V0 + (size_t)(kt & 1) * KV_BYTES);

        if (!skip) {
            // ---- S strip = Qstrip @ K^T ----
#pragma unroll
            for (int nt = 0; nt < 4; ++nt) {
                wmma::fragment<wmma::accumulator, 16, 16, 8, float> s;
                wmma::fill_fragment(s, 0.f);
#pragma unroll
                for (int ks = 0; ks < 8; ++ks) {
                    wmma::fragment<wmma::matrix_b, 16, 16, 8, wmma::precision::tf32,
                                   wmma::col_major> bf;
                    wmma::load_matrix_sync(bf, Ks + (size_t)(nt * 16) * F_LD + ks * 8,
                                           F_LD);
                    wmma::mma_sync(s, qa[ks], bf, s);
                }
                if (!mask) {
#pragma unroll
                    for (int e = 0; e < s.num_elements; ++e) s.x[e] = __expf(s.x[e]);
                }
                wmma::store_matrix_sync(Ps + (size_t)sr0 * F_LD + nt * 16, s, F_LD,
                                        wmma::mem_row_major);
            }
            __syncwarp();

            if (mask) {  // scalar mask + exp on own 16-row strip
                const int rl = l >> 1;
                const int row = sr0 + rl;
                const int c0 = (l & 1) * 32;
                float* Srow = Ps + (size_t)row * F_LD + c0;
                const int qg = qt * 128 + row;
                const int jg0 = kt * 64 + c0;
#pragma unroll
                for (int i = 0; i < 8; ++i) {
                    float4 v = *(float4*)(Srow + i * 4);
                    int j = jg0 + i * 4;
                    v.x = (j + 0 > qg) ? 0.f : __expf(v.x);
                    v.y = (j + 1 > qg) ? 0.f : __expf(v.y);
                    v.z = (j + 2 > qg) ? 0.f : __expf(v.z);
                    v.w = (j + 3 > qg) ? 0.f : __expf(v.w);
                    *(float4*)(Srow + i * 4) = v;
                }
                __syncwarp();
            }

            // ---- O strip += P @ V ; l strip += P @ ones ----
#pragma unroll
            for (int ks = 0; ks < 8; ++ks) {
                wmma::fragment<wmma::matrix_a, 16, 16, 8, wmma::precision::tf32,
                               wmma::row_major> pa;
                wmma::load_matrix_sync(pa, Ps + (size_t)sr0 * F_LD + ks * 8, F_LD);
#pragma unroll
                for (int nt = 0; nt < 4; ++nt) {
                    wmma::fragment<wmma::matrix_b, 16, 16, 8, wmma::precision::tf32,
                                   wmma::row_major> vb;
                    wmma::load_matrix_sync(vb, Vs + (size_t)(ks * 8) * F_LD + nt * 16,
                                           F_LD);
                    wmma::mma_sync(oacc[nt], pa, vb, oacc[nt]);
                }
                wmma::mma_sync(lacc, pa, b_ones, lacc);
            }
        }
        __syncthreads();   // all warps done with buffers (kt) before reuse
    }

    // ---- epilogue: O / l -> fp16 ctx (Ls aliases dead K0 buffer) ----
#pragma unroll
    for (int nt = 0; nt < 4; ++nt)
        wmma::store_matrix_sync(Ps + (size_t)sr0 * F_LD + nt * 16, oacc[nt], F_LD,
                                wmma::mem_row_major);
    wmma::store_matrix_sync(Ls + (size_t)w * 256, lacc, 16, wmma::mem_row_major);
    __syncthreads();

    {
        const int row = tid >> 1;            // 128 rows, 2 threads/row
        const int c0 = (tid & 1) * 32;
        const float inv = 1.f / Ls[(size_t)(row >> 4) * 256 + (row & 15) * 16];
        __half* Og = O + (size_t)(b * TT + qt * 128 + row) * D_MODEL + headoff + c0;
        const float* Sr = Ps + (size_t)row * F_LD + c0;
#pragma unroll
        for (int i = 0; i < 4; ++i) {
            float4 v = *(const float4*)(Sr + i * 8);
            float4 v2 = *(const float4*)(Sr + i * 8 + 4);
            __half2 h0 = __floats2half2_rn(v.x * inv, v.y * inv);
            __half2 h1 = __floats2half2_rn(v.z * inv, v.w * inv);
            __half2 h2 = __floats2half2_rn(v2.x * inv, v2.y * inv);
            __half2 h3 = __floats2half2_rn(v2.z * inv, v2.w * inv);
            uint4 o;
            o.x = *(uint32_t*)&h0; o.y = *(uint32_t*)&h1;
            o.z = *(uint32_t*)&h2; o.w = *(uint32_t*)&h3;
            *(uint4*)(Og + i * 8) = o;
        }
    }
}

// ---------------------------------------------------------------------------
extern "C" void kernel_launch(void* const* d_in, const int* in_sizes, int n_in,
                              void* d_out, int out_size) {
    const float* x = (const float*)d_in[0];
    const float* Wq = (const float*)d_in[1];
    const float* Wk = (const float*)d_in[2];
    const float* Wv = (const float*)d_in[3];
    const float* Wo = (const float*)d_in[4];
    const float* bo = (const float*)d_in[5];
    float* out = (float*)d_out;

    __half *dXh, *dWh, *dChh;
    float *dQ, *dK, *dV;
    cudaGetSymbolAddress((void**)&dXh, g_Xh);
    cudaGetSymbolAddress((void**)&dWh, g_Wh);
    cudaGetSymbolAddress((void**)&dChh, g_Chh);
    cudaGetSymbolAddress((void**)&dQ, g_Q);
    cudaGetSymbolAddress((void**)&dK, g_K);
    cudaGetSymbolAddress((void**)&dV, g_V);
    __half* dWqh = dWh;
    __half* dWkh = dWh + (size_t)D_MODEL * D_MODEL;
    __half* dWvh = dWh + 2 * (size_t)D_MODEL * D_MODEL;
    __half* dWoh = dWh + 3 * (size_t)D_MODEL * D_MODEL;

    cudaFuncSetAttribute(gemm_qkv, cudaFuncAttributeMaxDynamicSharedMemorySize,
                         G_SMEM_BYTES);
    cudaFuncSetAttribute(gemm_o, cudaFuncAttributeMaxDynamicSharedMemorySize,
                         G_SMEM_BYTES);
    cudaFuncSetAttribute(flash_t, cudaFuncAttributeMaxDynamicSharedMemorySize,
                         F_SMEM_BYTES);

    const int nx4 = BT * D_MODEL / 4;
    const int nw4 = D_MODEL * D_MODEL / 4;
    conv_f2h<<<(nx4 + 255) / 256, 256>>>((const float4*)x, (uint2*)dXh, nx4);
    dim3 w4_grid((nw4 + 255) / 256, 4);
    conv_w4<<<w4_grid, 256>>>((const float4*)Wq, (const float4*)Wk,
                              (const float4*)Wv, (const float4*)Wo,
                              (uint2*)dWh, nw4);

    // fused QKV projection: one launch, 24x64 CTAs
    dim3 qkv_grid(3 * (D_MODEL / BN), BT / BM);  // (24, 64)
    gemm_qkv<<<qkv_grid, 256, G_SMEM_BYTES>>>(dXh, dWqh, dWkh, dWvh, dQ, dK, dV);

    // flash: heavy q-tiles scheduled first (qt reversed on slow axis)
    dim3 attn_grid(BB * N_HEADS, TT / 128);  // (64, 16)
    flash_t<<<attn_grid, 256, F_SMEM_BYTES>>>(dQ, dK, dV, dChh);

    dim3 gemm_grid(D_MODEL / BN, BT / BM);  // (8, 64)
    gemm_o<<<gemm_grid, 256, G_SMEM_BYTES>>>(dChh, dWoh, out, bo);
}

// round 14
// speedup vs baseline: 1.0806x; 1.0806x over previous
#include <cuda_runtime.h>
#include <cuda_fp16.h>
#include <mma.h>
#include <cstdint>

using namespace nvcuda;

#define D_MODEL 1024
#define N_HEADS 16
#define HEAD_DIM 64
#define BB 4
#define TT 2048
#define BT (BB * TT)  // 8192

// ---------------- scratch (__device__ globals; no allocs allowed) ----------
__device__ __half g_Xh[(size_t)BT * D_MODEL];
__device__ __half g_Wh[4][(size_t)D_MODEL * D_MODEL];
__device__ __half g_Chh[(size_t)BT * D_MODEL];
__device__ float g_Q[(size_t)BT * D_MODEL];   // tf32-rounded
__device__ float g_K[(size_t)BT * D_MODEL];   // tf32-rounded
__device__ float g_V[(size_t)BT * D_MODEL];   // tf32-rounded

// ---------------- helpers ---------------------------------------------------
__device__ __forceinline__ uint32_t smem_u32(const void* p) {
    uint32_t a;
    asm("{ .reg .u64 t; cvta.to.shared.u64 t, %1; cvt.u32.u64 %0, t; }"
        : "=r"(a) : "l"(p));
    return a;
}
#define CP_ASYNC16(dst, src) \
    asm volatile("cp.async.cg.shared.global [%0], [%1], 16;" :: "r"(dst), "l"(src) : "memory")
#define CP_ASYNC_COMMIT() asm volatile("cp.async.commit_group;" ::: "memory")
#define CP_ASYNC_WAIT0() asm volatile("cp.async.wait_group 0;" ::: "memory")
#define CP_ASYNC_WAIT1() asm volatile("cp.async.wait_group 1;" ::: "memory")

// ---------------- fp32 -> fp16 pre-converts ---------------------------------
__global__ __launch_bounds__(256) void conv_f2h(const float4* __restrict__ in,
                                                uint2* __restrict__ out, int n4) {
    int i = blockIdx.x * 256 + threadIdx.x;
    if (i < n4) {
        float4 v = in[i];
        __half2 a = __floats2half2_rn(v.x, v.y);
        __half2 b = __floats2half2_rn(v.z, v.w);
        uint2 o;
        o.x = *(uint32_t*)&a;
        o.y = *(uint32_t*)&b;
        out[i] = o;
    }
}

// all four weight matrices in one launch (blockIdx.y selects the matrix)
__global__ __launch_bounds__(256) void conv_w4(const float4* __restrict__ w0,
                                               const float4* __restrict__ w1,
                                               const float4* __restrict__ w2,
                                               const float4* __restrict__ w3,
                                               uint2* __restrict__ outbase, int n4) {
    const float4* in = (blockIdx.y == 0) ? w0 : (blockIdx.y == 1) ? w1
                       : (blockIdx.y == 2) ? w2 : w3;
    uint2* out = outbase + (size_t)blockIdx.y * n4;
    int i = blockIdx.x * 256 + threadIdx.x;
    if (i < n4) {
        float4 v = in[i];
        __half2 a = __floats2half2_rn(v.x, v.y);
        __half2 b = __floats2half2_rn(v.z, v.w);
        uint2 o;
        o.x = *(uint32_t*)&a;
        o.y = *(uint32_t*)&b;
        out[i] = o;
    }
}

// ---------------------------------------------------------------------------
// fp16 WMMA GEMM core (proven R8-R12 datapath).
// OUT_TF32: round output to tf32. else: +bias fp32 out.
// ---------------------------------------------------------------------------
#define BM 128
#define BN 128
#define BK 32
#define A_LDH 40
#define B_LDH 136
#define C_LDF 136
#define A_BYTES (BM * A_LDH * 2)
#define B_BYTES (BK * B_LDH * 2)
#define BUF_BYTES (A_BYTES + B_BYTES)
#define G_SMEM_BYTES (BM * C_LDF * 4)
#define G_NCHUNK (D_MODEL / BK)

template <int OUT_TF32>
__device__ __forceinline__ void gemm_body(const __half* __restrict__ A,
                                          const __half* __restrict__ Bm,
                                          float* __restrict__ C,
                                          const float* __restrict__ bias,
                                          int bm, int bn, float* sm) {
    const int tid = threadIdx.x;
    const int wid = tid >> 5;
    const int warp_m = wid >> 1;
    const int warp_n = wid & 1;
    const uint32_t sbase = smem_u32(sm);

    wmma::fragment<wmma::accumulator, 16, 16, 16, float> acc[2][4];
#pragma unroll
    for (int i = 0; i < 2; ++i)
#pragma unroll
        for (int j = 0; j < 4; ++j) wmma::fill_fragment(acc[i][j], 0.f);

    const __half* Ab = A + (size_t)bm * D_MODEL;
    const __half* Bb = Bm + bn;

    auto issue = [&](int c) {
        const uint32_t buf = sbase + (uint32_t)(c & 1) * BUF_BYTES;
        const __half* Ag = Ab + c * BK;
        const __half* Bg = Bb + (size_t)(c * BK) * D_MODEL;
#pragma unroll
        for (int i = 0; i < 2; ++i) {
            int idx = i * 256 + tid;
            int row = idx >> 2, seg = idx & 3;
            CP_ASYNC16(buf + (uint32_t)(row * A_LDH + seg * 8) * 2,
                       Ag + (size_t)row * D_MODEL + seg * 8);
        }
#pragma unroll
        for (int i = 0; i < 2; ++i) {
            int idx = i * 256 + tid;
            int row = idx >> 4, seg = idx & 15;
            CP_ASYNC16(buf + A_BYTES + (uint32_t)(row * B_LDH + seg * 8) * 2,
                       Bg + (size_t)row * D_MODEL + seg * 8);
        }
        CP_ASYNC_COMMIT();
    };

    issue(0);
    for (int c = 0; c < G_NCHUNK; ++c) {
        if (c + 1 < G_NCHUNK) {
            issue(c + 1);
            CP_ASYNC_WAIT1();
        } else {
            CP_ASYNC_WAIT0();
        }
        __syncthreads();

        const __half* As = (const __half*)((const char*)sm + (size_t)(c & 1) * BUF_BYTES);
        const __half* Bs = As + A_BYTES / 2;

#pragma unroll
        for (int ks = 0; ks < BK / 16; ++ks) {
            wmma::fragment<wmma::matrix_a, 16, 16, 16, __half, wmma::row_major> a[2];
            wmma::fragment<wmma::matrix_b, 16, 16, 16, __half, wmma::row_major> b[4];
#pragma unroll
            for (int i = 0; i < 2; ++i)
                wmma::load_matrix_sync(
                    a[i], As + (size_t)(warp_m * 32 + i * 16) * A_LDH + ks * 16, A_LDH);
#pragma unroll
            for (int j = 0; j < 4; ++j)
                wmma::load_matrix_sync(
                    b[j], Bs + (size_t)(ks * 16) * B_LDH + warp_n * 64 + j * 16, B_LDH);
#pragma unroll
            for (int i = 0; i < 2; ++i)
#pragma unroll
                for (int j = 0; j < 4; ++j)
                    wmma::mma_sync(acc[i][j], a[i], b[j], acc[i][j]);
        }
        __syncthreads();
    }

    float* Cs = sm;
#pragma unroll
    for (int i = 0; i < 2; ++i)
#pragma unroll
        for (int j = 0; j < 4; ++j)
            wmma::store_matrix_sync(
                Cs + (size_t)(warp_m * 32 + i * 16) * C_LDF + warp_n * 64 + j * 16,
                acc[i][j], C_LDF, wmma::mem_row_major);
    __syncthreads();

#pragma unroll
    for (int i = 0; i < 16; ++i) {
        int idx = i * 256 + tid;
        int row = idx >> 5, c4 = (idx & 31) * 4;
        float4 v = *(const float4*)(Cs + (size_t)row * C_LDF + c4);
        if (OUT_TF32) {
            uint4 o;
            asm("cvt.rna.tf32.f32 %0, %1;" : "=r"(o.x) : "f"(v.x));
            asm("cvt.rna.tf32.f32 %0, %1;" : "=r"(o.y) : "f"(v.y));
            asm("cvt.rna.tf32.f32 %0, %1;" : "=r"(o.z) : "f"(v.z));
            asm("cvt.rna.tf32.f32 %0, %1;" : "=r"(o.w) : "f"(v.w));
            *(uint4*)(C + (size_t)(bm + row) * D_MODEL + bn + c4) = o;
        } else {
            v.x += bias[bn + c4 + 0];
            v.y += bias[bn + c4 + 1];
            v.z += bias[bn + c4 + 2];
            v.w += bias[bn + c4 + 3];
            *(float4*)(C + (size_t)(bm + row) * D_MODEL + bn + c4) = v;
        }
    }
}

// fused Q/K/V projection
__global__ __launch_bounds__(256) void gemm_qkv(const __half* __restrict__ A,
                                                const __half* __restrict__ W0,
                                                const __half* __restrict__ W1,
                                                const __half* __restrict__ W2,
                                                float* __restrict__ C0,
                                                float* __restrict__ C1,
                                                float* __restrict__ C2) {
    extern __shared__ float sm[];
    const int which = blockIdx.x >> 3;
    const int bn = (blockIdx.x & 7) * BN;
    const int bm = blockIdx.y * BM;
    const __half* Bm = (which == 0) ? W0 : (which == 1) ? W1 : W2;
    float* C = (which == 0) ? C0 : (which == 1) ? C1 : C2;
    gemm_body<1>(A, Bm, C, nullptr, bm, bn, sm);
}

// O projection (+bias)
__global__ __launch_bounds__(256) void gemm_o(const __half* __restrict__ A,
                                              const __half* __restrict__ Bm,
                                              float* __restrict__ C,
                                              const float* __restrict__ bias) {
    extern __shared__ float sm[];
    gemm_body<0>(A, Bm, C, bias, blockIdx.y * BM, blockIdx.x * BN, sm);
}

// ---------------------------------------------------------------------------
// tf32 WMMA flash attention (causal) — R13 structure with the register cap
// that actually enables 2 CTAs/SM: __launch_bounds__(256, 2) => <=128 regs,
// 2 CTAs x 256 thr = 512 thr = full 64K regfile => 16 warps/SM.
// 8 warps x 16-row strips, 128-row q tile, K0/K1+V0/V1 double buffers,
// one combined commit group per tile, 2 syncs/tile. qt reversed.
// ---------------------------------------------------------------------------
#define F_LD 68
#define KV_BYTES (64 * F_LD * 4)            // 17408
#define OFF_K0 0
#define OFF_V0 (2 * KV_BYTES)               // 34816 (V0/V1 follow K0/K1)
#define OFF_PB (4 * KV_BYTES)               // 69632 (S/P/O staging, 128 x F_LD)
#define OFF_ONE (OFF_PB + 128 * F_LD * 4)   // 104448 (8x16 ones)
#define F_SMEM_BYTES (OFF_ONE + 512)        // 104960 (102.5KB) -> 2 CTAs/SM

__global__ __launch_bounds__(256, 2) void flash_t(const float* __restrict__ Q,
                                                  const float* __restrict__ K,
                                                  const float* __restrict__ V,
                                                  __half* __restrict__ O) {
    extern __shared__ char smb[];
    float* Ps = (float*)(smb + OFF_PB);
    float* Ones = (float*)(smb + OFF_ONE);
    float* Ls = (float*)(smb + OFF_K0);   // aliased onto K0 (epilogue only)

    const int tid = threadIdx.x;
    const int w = tid >> 5;               // 0..7
    const int l = tid & 31;
    const int qt = (int)(gridDim.y - 1 - blockIdx.y);  // heavy tiles first
    const int bh = blockIdx.x;
    const int b = bh >> 4;
    const int h = bh & 15;

    const size_t headoff = (size_t)h * HEAD_DIM;
    const uint32_t sbase = smem_u32(smb);
    const int sr0 = w * 16;               // warp strip base row (16 rows)

    // ---- stage Q*0.125 (exact scale; stays tf32) + ones ----
    {
        const float* Qg = Q + (size_t)(b * TT + qt * 128) * D_MODEL + headoff;
        for (int idx = tid; idx < 128 * 16; idx += 256) {
            int row = idx >> 4, c4 = (idx & 15) * 4;
            float4 v = *(const float4*)(Qg + (size_t)row * D_MODEL + c4);
            v.x *= 0.125f; v.y *= 0.125f; v.z *= 0.125f; v.w *= 0.125f;
            *(float4*)(Ps + (size_t)row * F_LD + c4) = v;
        }
        if (tid < 128) Ones[tid] = 1.0f;  // 8x16 = 128 floats
    }
    __syncthreads();

    wmma::fragment<wmma::matrix_a, 16, 16, 8, wmma::precision::tf32,
                   wmma::row_major> qa[8];
#pragma unroll
    for (int ks = 0; ks < 8; ++ks)
        wmma::load_matrix_sync(qa[ks], Ps + (size_t)sr0 * F_LD + ks * 8, F_LD);

    wmma::fragment<wmma::matrix_b, 16, 16, 8, wmma::precision::tf32,
                   wmma::row_major> b_ones;
    wmma::load_matrix_sync(b_ones, Ones, 16);

    wmma::fragment<wmma::accumulator, 16, 16, 8, float> oacc[4], lacc;
#pragma unroll
    for (int n = 0; n < 4; ++n) wmma::fill_fragment(oacc[n], 0.f);
    wmma::fill_fragment(lacc, 0.f);

    const float* Kb = K + (size_t)(b * TT) * D_MODEL + headoff;
    const float* Vb = V + (size_t)(b * TT) * D_MODEL + headoff;

    // combined K+V tile load, ONE commit group (256 threads)
    auto issueKV = [&](int t) {
        const uint32_t kbuf = sbase + OFF_K0 + (uint32_t)(t & 1) * KV_BYTES;
        const uint32_t vbuf = sbase + OFF_V0 + (uint32_t)(t & 1) * KV_BYTES;
        const float* Kg = Kb + (size_t)(t * 64) * D_MODEL;
        const float* Vg = Vb + (size_t)(t * 64) * D_MODEL;
#pragma unroll
        for (int i = 0; i < 4; ++i) {
            int idx = i * 256 + tid;
            int row = idx >> 4, c4 = (idx & 15) * 4;
            uint32_t off = (uint32_t)(row * F_LD + c4) * 4;
            CP_ASYNC16(kbuf + off, Kg + (size_t)row * D_MODEL + c4);
            CP_ASYNC16(vbuf + off, Vg + (size_t)row * D_MODEL + c4);
        }
        CP_ASYNC_COMMIT();
    };

    issueKV(0);

    const int nkt = 2 * qt + 2;

    for (int kt = 0; kt < nkt; ++kt) {
        CP_ASYNC_WAIT0();   // only group(kt) pending here
        __syncthreads();    // K(kt), V(kt) visible to all warps

        if (kt + 1 < nkt) issueKV(kt + 1);  // overlaps this whole tile

        // causal role of this warp for this tile (16-row strips)
        const bool skip = (kt == 2 * qt + 1) && (w < 4);
        const bool mask = ((kt == 2 * qt) && (w < 4)) ||
                          ((kt == 2 * qt + 1) && (w >= 4));

        const float* Ks = (const float*)(smb + OFF_K0 + (size_t)(kt & 1) * KV_BYTES);
        const float* Vs = (const float*)(smb + OFF_V0 + (size_t)(kt & 1) * KV_BYTES);

        if (!skip) {
            // ---- S strip = Qstrip @ K^T ----
#pragma unroll
            for (int nt = 0; nt < 4; ++nt) {
                wmma::fragment<wmma::accumulator, 16, 16, 8, float> s;
                wmma::fill_fragment(s, 0.f);
#pragma unroll
                for (int ks = 0; ks < 8; ++ks) {
                    wmma::fragment<wmma::matrix_b, 16, 16, 8, wmma::precision::tf32,
                                   wmma::col_major> bf;
                    wmma::load_matrix_sync(bf, Ks + (size_t)(nt * 16) * F_LD + ks * 8,
                                           F_LD);
                    wmma::mma_sync(s, qa[ks], bf, s);
                }
                if (!mask) {
#pragma unroll
                    for (int e = 0; e < s.num_elements; ++e) s.x[e] = __expf(s.x[e]);
                }
                wmma::store_matrix_sync(Ps + (size_t)sr0 * F_LD + nt * 16, s, F_LD,
                                        wmma::mem_row_major);
            }
            __syncwarp();

            if (mask) {  // scalar mask + exp on own 16-row strip
                const int rl = l >> 1;
                const int row = sr0 + rl;
                const int c0 = (l & 1) * 32;
                float* Srow = Ps + (size_t)row * F_LD + c0;
                const int qg = qt * 128 + row;
                const int jg0 = kt * 64 + c0;
#pragma unroll
                for (int i = 0; i < 8; ++i) {
                    float4 v = *(float4*)(Srow + i * 4);
                    int j = jg0 + i * 4;
                    v.x = (j + 0 > qg) ? 0.f : __expf(v.x);
                    v.y = (j + 1 > qg) ? 0.f : __expf(v.y);
                    v.z = (j + 2 > qg) ? 0.f : __expf(v.z);
                    v.w = (j + 3 > qg) ? 0.f : __expf(v.w);
                    *(float4*)(Srow + i * 4) = v;
                }
                __syncwarp();
            }

            // ---- O strip += P @ V ; l strip += P @ ones ----
#pragma unroll
            for (int ks = 0; ks < 8; ++ks) {
                wmma::fragment<wmma::matrix_a, 16, 16, 8, wmma::precision::tf32,
                               wmma::row_major> pa;
                wmma::load_matrix_sync(pa, Ps + (size_t)sr0 * F_LD + ks * 8, F_LD);
#pragma unroll
                for (int nt = 0; nt < 4; ++nt) {
                    wmma::fragment<wmma::matrix_b, 16, 16, 8, wmma::precision::tf32,
                                   wmma::row_major> vb;
                    wmma::load_matrix_sync(vb, Vs + (size_t)(ks * 8) * F_LD + nt * 16,
                                           F_LD);
                    wmma::mma_sync(oacc[nt], pa, vb, oacc[nt]);
                }
                wmma::mma_sync(lacc, pa, b_ones, lacc);
            }
        }
        __syncthreads();   // all warps done with buffers (kt) before reuse
    }

    // ---- epilogue: O / l -> fp16 ctx (Ls aliases dead K0 buffer) ----
#pragma unroll
    for (int nt = 0; nt < 4; ++nt)
        wmma::store_matrix_sync(Ps + (size_t)sr0 * F_LD + nt * 16, oacc[nt], F_LD,
                                wmma::mem_row_major);
    wmma::store_matrix_sync(Ls + (size_t)w * 256, lacc, 16, wmma::mem_row_major);
    __syncthreads();

    {
        const int row = tid >> 1;            // 128 rows, 2 threads/row
        const int c0 = (tid & 1) * 32;
        const float inv = 1.f / Ls[(size_t)(row >> 4) * 256 + (row & 15) * 16];
        __half* Og = O + (size_t)(b * TT + qt * 128 + row) * D_MODEL + headoff + c0;
        const float* Sr = Ps + (size_t)row * F_LD + c0;
#pragma unroll
        for (int i = 0; i < 4; ++i) {
            float4 v = *(const float4*)(Sr + i * 8);
            float4 v2 = *(const float4*)(Sr + i * 8 + 4);
            __half2 h0 = __floats2half2_rn(v.x * inv, v.y * inv);
            __half2 h1 = __floats2half2_rn(v.z * inv, v.w * inv);
            __half2 h2 = __floats2half2_rn(v2.x * inv, v2.y * inv);
            __half2 h3 = __floats2half2_rn(v2.z * inv, v2.w * inv);
            uint4 o;
            o.x = *(uint32_t*)&h0; o.y = *(uint32_t*)&h1;
            o.z = *(uint32_t*)&h2; o.w = *(uint32_t*)&h3;
            *(uint4*)(Og + i * 8) = o;
        }
    }
}

// ---------------------------------------------------------------------------
extern "C" void kernel_launch(void* const* d_in, const int* in_sizes, int n_in,
                              void* d_out, int out_size) {
    const float* x = (const float*)d_in[0];
    const float* Wq = (const float*)d_in[1];
    const float* Wk = (const float*)d_in[2];
    const float* Wv = (const float*)d_in[3];
    const float* Wo = (const float*)d_in[4];
    const float* bo = (const float*)d_in[5];
    float* out = (float*)d_out;

    __half *dXh, *dWh, *dChh;
    float *dQ, *dK, *dV;
    cudaGetSymbolAddress((void**)&dXh, g_Xh);
    cudaGetSymbolAddress((void**)&dWh, g_Wh);
    cudaGetSymbolAddress((void**)&dChh, g_Chh);
    cudaGetSymbolAddress((void**)&dQ, g_Q);
    cudaGetSymbolAddress((void**)&dK, g_K);
    cudaGetSymbolAddress((void**)&dV, g_V);
    __half* dWqh = dWh;
    __half* dWkh = dWh + (size_t)D_MODEL * D_MODEL;
    __half* dWvh = dWh + 2 * (size_t)D_MODEL * D_MODEL;
    __half* dWoh = dWh + 3 * (size_t)D_MODEL * D_MODEL;

    cudaFuncSetAttribute(gemm_qkv, cudaFuncAttributeMaxDynamicSharedMemorySize,
                         G_SMEM_BYTES);
    cudaFuncSetAttribute(gemm_o, cudaFuncAttributeMaxDynamicSharedMemorySize,
                         G_SMEM_BYTES);
    cudaFuncSetAttribute(flash_t, cudaFuncAttributeMaxDynamicSharedMemorySize,
                         F_SMEM_BYTES);

    const int nx4 = BT * D_MODEL / 4;
    const int nw4 = D_MODEL * D_MODEL / 4;
    conv_f2h<<<(nx4 + 255) / 256, 256>>>((const float4*)x, (uint2*)dXh, nx4);
    dim3 w4_grid((nw4 + 255) / 256, 4);
    conv_w4<<<w4_grid, 256>>>((const float4*)Wq, (const float4*)Wk,
                              (const float4*)Wv, (const float4*)Wo,
                              (uint2*)dWh, nw4);

    // fused QKV projection: one launch, 24x64 CTAs
    dim3 qkv_grid(3 * (D_MODEL / BN), BT / BM);  // (24, 64)
    gemm_qkv<<<qkv_grid, 256, G_SMEM_BYTES>>>(dXh, dWqh, dWkh, dWvh, dQ, dK, dV);

    // flash: heavy q-tiles scheduled first (qt reversed on slow axis)
    dim3 attn_grid(BB * N_HEADS, TT / 128);  // (64, 16)
    flash_t<<<attn_grid, 256, F_SMEM_BYTES>>>(dQ, dK, dV, dChh);

    dim3 gemm_grid(D_MODEL / BN, BT / BM);  // (8, 64)
    gemm_o<<<gemm_grid, 256, G_SMEM_BYTES>>>(dChh, dWoh, out, bo);
}

// round 15
// speedup vs baseline: 1.1620x; 1.0754x over previous
#include <cuda_runtime.h>
#include <cuda_fp16.h>
#include <mma.h>
#include <cstdint>

using namespace nvcuda;

#define D_MODEL 1024
#define N_HEADS 16
#define HEAD_DIM 64
#define BB 4
#define TT 2048
#define BT (BB * TT)  // 8192

// ---------------- scratch (__device__ globals; no allocs allowed) ----------
__device__ __half g_Xh[(size_t)BT * D_MODEL];
__device__ __half g_Wh[4][(size_t)D_MODEL * D_MODEL];
__device__ __half g_Chh[(size_t)BT * D_MODEL];
__device__ float g_Q[(size_t)BT * D_MODEL];   // tf32-rounded
__device__ float g_K[(size_t)BT * D_MODEL];   // tf32-rounded
__device__ float g_V[(size_t)BT * D_MODEL];   // tf32-rounded

// ---------------- helpers ---------------------------------------------------
__device__ __forceinline__ uint32_t smem_u32(const void* p) {
    uint32_t a;
    asm("{ .reg .u64 t; cvta.to.shared.u64 t, %1; cvt.u32.u64 %0, t; }"
        : "=r"(a) : "l"(p));
    return a;
}
#define CP_ASYNC16(dst, src) \
    asm volatile("cp.async.cg.shared.global [%0], [%1], 16;" :: "r"(dst), "l"(src) : "memory")
#define CP_ASYNC_COMMIT() asm volatile("cp.async.commit_group;" ::: "memory")
#define CP_ASYNC_WAIT0() asm volatile("cp.async.wait_group 0;" ::: "memory")
#define CP_ASYNC_WAIT1() asm volatile("cp.async.wait_group 1;" ::: "memory")

// ---------------- fp32 -> fp16 pre-converts ---------------------------------
__global__ __launch_bounds__(256) void conv_f2h(const float4* __restrict__ in,
                                                uint2* __restrict__ out, int n4) {
    int i = blockIdx.x * 256 + threadIdx.x;
    if (i < n4) {
        float4 v = in[i];
        __half2 a = __floats2half2_rn(v.x, v.y);
        __half2 b = __floats2half2_rn(v.z, v.w);
        uint2 o;
        o.x = *(uint32_t*)&a;
        o.y = *(uint32_t*)&b;
        out[i] = o;
    }
}

// all four weight matrices in one launch (blockIdx.y selects the matrix)
__global__ __launch_bounds__(256) void conv_w4(const float4* __restrict__ w0,
                                               const float4* __restrict__ w1,
                                               const float4* __restrict__ w2,
                                               const float4* __restrict__ w3,
                                               uint2* __restrict__ outbase, int n4) {
    const float4* in = (blockIdx.y == 0) ? w0 : (blockIdx.y == 1) ? w1
                       : (blockIdx.y == 2) ? w2 : w3;
    uint2* out = outbase + (size_t)blockIdx.y * n4;
    int i = blockIdx.x * 256 + threadIdx.x;
    if (i < n4) {
        float4 v = in[i];
        __half2 a = __floats2half2_rn(v.x, v.y);
        __half2 b = __floats2half2_rn(v.z, v.w);
        uint2 o;
        o.x = *(uint32_t*)&a;
        o.y = *(uint32_t*)&b;
        out[i] = o;
    }
}

// ---------------------------------------------------------------------------
// fp16 WMMA GEMM core — BK=64: half the chunks/syncs of the R12 version,
// identical k-ascending accumulation order (bit-identical results).
// OUT_TF32: round output to tf32. else: +bias fp32 out.
// ---------------------------------------------------------------------------
#define BM 128
#define BN 128
#define BK 64
#define A_LDH 72
#define B_LDH 136
#define C_LDF 136
#define A_BYTES (BM * A_LDH * 2)            // 18432
#define B_BYTES (BK * B_LDH * 2)            // 17408
#define BUF_BYTES (A_BYTES + B_BYTES)       // 35840
#define G_SMEM_BYTES (2 * BUF_BYTES)        // 71680 (>= 128*136*4 epilogue)
#define G_NCHUNK (D_MODEL / BK)             // 16

template <int OUT_TF32>
__device__ __forceinline__ void gemm_body(const __half* __restrict__ A,
                                          const __half* __restrict__ Bm,
                                          float* __restrict__ C,
                                          const float* __restrict__ bias,
                                          int bm, int bn, float* sm) {
    const int tid = threadIdx.x;
    const int wid = tid >> 5;
    const int warp_m = wid >> 1;
    const int warp_n = wid & 1;
    const uint32_t sbase = smem_u32(sm);

    wmma::fragment<wmma::accumulator, 16, 16, 16, float> acc[2][4];
#pragma unroll
    for (int i = 0; i < 2; ++i)
#pragma unroll
        for (int j = 0; j < 4; ++j) wmma::fill_fragment(acc[i][j], 0.f);

    const __half* Ab = A + (size_t)bm * D_MODEL;
    const __half* Bb = Bm + bn;

    auto issue = [&](int c) {
        const uint32_t buf = sbase + (uint32_t)(c & 1) * BUF_BYTES;
        const __half* Ag = Ab + c * BK;
        const __half* Bg = Bb + (size_t)(c * BK) * D_MODEL;
        // A: 128 rows x 8 segs (8 halves each) = 1024 vectors
#pragma unroll
        for (int i = 0; i < 4; ++i) {
            int idx = i * 256 + tid;
            int row = idx >> 3, seg = idx & 7;
            CP_ASYNC16(buf + (uint32_t)(row * A_LDH + seg * 8) * 2,
                       Ag + (size_t)row * D_MODEL + seg * 8);
        }
        // B: 64 rows x 16 segs = 1024 vectors
#pragma unroll
        for (int i = 0; i < 4; ++i) {
            int idx = i * 256 + tid;
            int row = idx >> 4, seg = idx & 15;
            CP_ASYNC16(buf + A_BYTES + (uint32_t)(row * B_LDH + seg * 8) * 2,
                       Bg + (size_t)row * D_MODEL + seg * 8);
        }
        CP_ASYNC_COMMIT();
    };

    issue(0);
    for (int c = 0; c < G_NCHUNK; ++c) {
        if (c + 1 < G_NCHUNK) {
            issue(c + 1);
            CP_ASYNC_WAIT1();
        } else {
            CP_ASYNC_WAIT0();
        }
        __syncthreads();

        const __half* As = (const __half*)((const char*)sm + (size_t)(c & 1) * BUF_BYTES);
        const __half* Bs = As + A_BYTES / 2;

#pragma unroll
        for (int ks = 0; ks < BK / 16; ++ks) {
            wmma::fragment<wmma::matrix_a, 16, 16, 16, __half, wmma::row_major> a[2];
            wmma::fragment<wmma::matrix_b, 16, 16, 16, __half, wmma::row_major> b[4];
#pragma unroll
            for (int i = 0; i < 2; ++i)
                wmma::load_matrix_sync(
                    a[i], As + (size_t)(warp_m * 32 + i * 16) * A_LDH + ks * 16, A_LDH);
#pragma unroll
            for (int j = 0; j < 4; ++j)
                wmma::load_matrix_sync(
                    b[j], Bs + (size_t)(ks * 16) * B_LDH + warp_n * 64 + j * 16, B_LDH);
#pragma unroll
            for (int i = 0; i < 2; ++i)
#pragma unroll
                for (int j = 0; j < 4; ++j)
                    wmma::mma_sync(acc[i][j], a[i], b[j], acc[i][j]);
        }
        __syncthreads();
    }

    float* Cs = sm;
#pragma unroll
    for (int i = 0; i < 2; ++i)
#pragma unroll
        for (int j = 0; j < 4; ++j)
            wmma::store_matrix_sync(
                Cs + (size_t)(warp_m * 32 + i * 16) * C_LDF + warp_n * 64 + j * 16,
                acc[i][j], C_LDF, wmma::mem_row_major);
    __syncthreads();

#pragma unroll
    for (int i = 0; i < 16; ++i) {
        int idx = i * 256 + tid;
        int row = idx >> 5, c4 = (idx & 31) * 4;
        float4 v = *(const float4*)(Cs + (size_t)row * C_LDF + c4);
        if (OUT_TF32) {
            uint4 o;
            asm("cvt.rna.tf32.f32 %0, %1;" : "=r"(o.x) : "f"(v.x));
            asm("cvt.rna.tf32.f32 %0, %1;" : "=r"(o.y) : "f"(v.y));
            asm("cvt.rna.tf32.f32 %0, %1;" : "=r"(o.z) : "f"(v.z));
            asm("cvt.rna.tf32.f32 %0, %1;" : "=r"(o.w) : "f"(v.w));
            *(uint4*)(C + (size_t)(bm + row) * D_MODEL + bn + c4) = o;
        } else {
            v.x += bias[bn + c4 + 0];
            v.y += bias[bn + c4 + 1];
            v.z += bias[bn + c4 + 2];
            v.w += bias[bn + c4 + 3];
            *(float4*)(C + (size_t)(bm + row) * D_MODEL + bn + c4) = v;
        }
    }
}

// fused Q/K/V projection
__global__ __launch_bounds__(256) void gemm_qkv(const __half* __restrict__ A,
                                                const __half* __restrict__ W0,
                                                const __half* __restrict__ W1,
                                                const __half* __restrict__ W2,
                                                float* __restrict__ C0,
                                                float* __restrict__ C1,
                                                float* __restrict__ C2) {
    extern __shared__ float sm[];
    const int which = blockIdx.x >> 3;
    const int bn = (blockIdx.x & 7) * BN;
    const int bm = blockIdx.y * BM;
    const __half* Bm = (which == 0) ? W0 : (which == 1) ? W1 : W2;
    float* C = (which == 0) ? C0 : (which == 1) ? C1 : C2;
    gemm_body<1>(A, Bm, C, nullptr, bm, bn, sm);
}

// O projection (+bias)
__global__ __launch_bounds__(256) void gemm_o(const __half* __restrict__ A,
                                              const __half* __restrict__ Bm,
                                              float* __restrict__ C,
                                              const float* __restrict__ bias) {
    extern __shared__ float sm[];
    gemm_body<0>(A, Bm, C, bias, blockIdx.y * BM, blockIdx.x * BN, sm);
}

// ---------------------------------------------------------------------------
// tf32 WMMA flash attention (causal) — EXACT R12 kernel (513us proven):
// 128 threads, 4 warps x 32-row strips, 128-row q tile, K0/K1+V0/V1 double
// buffers, one combined commit group per tile (issued at tile top),
// 2 syncthreads/tile. qt reversed (heavy first). Ls aliased onto K0.
// ---------------------------------------------------------------------------
#define F_LD 68
#define KV_BYTES (64 * F_LD * 4)            // 17408
#define OFF_K0 0
#define OFF_V0 (2 * KV_BYTES)               // 34816 (V0/V1 follow K0/K1)
#define OFF_PB (4 * KV_BYTES)               // 69632 (S/P/O staging, 128 x F_LD)
#define OFF_ONE (OFF_PB + 128 * F_LD * 4)   // 104448 (8x16 ones)
#define F_SMEM_BYTES (OFF_ONE + 512)        // 104960 (102.5KB) -> 2 CTAs/SM

__global__ __launch_bounds__(128) void flash_t(const float* __restrict__ Q,
                                               const float* __restrict__ K,
                                               const float* __restrict__ V,
                                               __half* __restrict__ O) {
    extern __shared__ char smb[];
    float* Ps = (float*)(smb + OFF_PB);
    float* Ones = (float*)(smb + OFF_ONE);
    float* Ls = (float*)(smb + OFF_K0);   // aliased onto K0 (epilogue only)

    const int tid = threadIdx.x;
    const int w = tid >> 5;
    const int l = tid & 31;
    const int qt = (int)(gridDim.y - 1 - blockIdx.y);  // heavy tiles first
    const int bh = blockIdx.x;
    const int b = bh >> 4;
    const int h = bh & 15;

    const size_t headoff = (size_t)h * HEAD_DIM;
    const uint32_t sbase = smem_u32(smb);
    const int sr0 = w * 32;      // warp strip base row

    // ---- stage Q*0.125 (exact scale; stays tf32) + ones ----
    {
        const float* Qg = Q + (size_t)(b * TT + qt * 128) * D_MODEL + headoff;
        for (int idx = tid; idx < 128 * 16; idx += 128) {
            int row = idx >> 4, c4 = (idx & 15) * 4;
            float4 v = *(const float4*)(Qg + (size_t)row * D_MODEL + c4);
            v.x *= 0.125f; v.y *= 0.125f; v.z *= 0.125f; v.w *= 0.125f;
            *(float4*)(Ps + (size_t)row * F_LD + c4) = v;
        }
        Ones[tid] = 1.0f;  // 8x16 = 128 floats
    }
    __syncthreads();

    wmma::fragment<wmma::matrix_a, 16, 16, 8, wmma::precision::tf32,
                   wmma::row_major> qa[2][8];
#pragma unroll
    for (int s2 = 0; s2 < 2; ++s2)
#pragma unroll
        for (int ks = 0; ks < 8; ++ks)
            wmma::load_matrix_sync(qa[s2][ks],
                                   Ps + (size_t)(sr0 + s2 * 16) * F_LD + ks * 8, F_LD);

    wmma::fragment<wmma::matrix_b, 16, 16, 8, wmma::precision::tf32,
                   wmma::row_major> b_ones;
    wmma::load_matrix_sync(b_ones, Ones, 16);

    wmma::fragment<wmma::accumulator, 16, 16, 8, float> oacc[2][4], lacc[2];
#pragma unroll
    for (int s2 = 0; s2 < 2; ++s2) {
#pragma unroll
        for (int n = 0; n < 4; ++n) wmma::fill_fragment(oacc[s2][n], 0.f);
        wmma::fill_fragment(lacc[s2], 0.f);
    }

    const float* Kb = K + (size_t)(b * TT) * D_MODEL + headoff;
    const float* Vb = V + (size_t)(b * TT) * D_MODEL + headoff;

    // combined K+V tile load, ONE commit group
    auto issueKV = [&](int t) {
        const uint32_t kbuf = sbase + OFF_K0 + (uint32_t)(t & 1) * KV_BYTES;
        const uint32_t vbuf = sbase + OFF_V0 + (uint32_t)(t & 1) * KV_BYTES;
        const float* Kg = Kb + (size_t)(t * 64) * D_MODEL;
        const float* Vg = Vb + (size_t)(t * 64) * D_MODEL;
#pragma unroll
        for (int i = 0; i < 8; ++i) {
            int idx = i * 128 + tid;
            int row = idx >> 4, c4 = (idx & 15) * 4;
            uint32_t off = (uint32_t)(row * F_LD + c4) * 4;
            CP_ASYNC16(kbuf + off, Kg + (size_t)row * D_MODEL + c4);
            CP_ASYNC16(vbuf + off, Vg + (size_t)row * D_MODEL + c4);
        }
        CP_ASYNC_COMMIT();
    };

    issueKV(0);

    const int nkt = 2 * qt + 2;

    for (int kt = 0; kt < nkt; ++kt) {
        CP_ASYNC_WAIT0();   // only group(kt) pending here
        __syncthreads();    // K(kt), V(kt) visible to all warps

        if (kt + 1 < nkt) issueKV(kt + 1);  // overlaps this whole tile

        // causal role of this warp for this tile
        const bool skip = (kt == 2 * qt + 1) && (w < 2);
        const bool mask = ((kt == 2 * qt) && (w < 2)) ||
                          ((kt == 2 * qt + 1) && (w >= 2));

        const float* Ks = (const float*)(smb + OFF_K0 + (size_t)(kt & 1) * KV_BYTES);
        const float* Vs = (const float*)(smb + OFF_V0 + (size_t)(kt & 1) * KV_BYTES);

        if (!skip) {
            // ---- S strips = Qstrips @ K^T (K fragments shared) ----
#pragma unroll
            for (int nt = 0; nt < 4; ++nt) {
                wmma::fragment<wmma::accumulator, 16, 16, 8, float> s0, s1;
                wmma::fill_fragment(s0, 0.f);
                wmma::fill_fragment(s1, 0.f);
#pragma unroll
                for (int ks = 0; ks < 8; ++ks) {
                    wmma::fragment<wmma::matrix_b, 16, 16, 8, wmma::precision::tf32,
                                   wmma::col_major> bf;
                    wmma::load_matrix_sync(bf, Ks + (size_t)(nt * 16) * F_LD + ks * 8,
                                           F_LD);
                    wmma::mma_sync(s0, qa[0][ks], bf, s0);
                    wmma::mma_sync(s1, qa[1][ks], bf, s1);
                }
                if (!mask) {
#pragma unroll
                    for (int e = 0; e < s0.num_elements; ++e) {
                        s0.x[e] = __expf(s0.x[e]);
                        s1.x[e] = __expf(s1.x[e]);
                    }
                }
                wmma::store_matrix_sync(Ps + (size_t)sr0 * F_LD + nt * 16, s0, F_LD,
                                        wmma::mem_row_major);
                wmma::store_matrix_sync(Ps + (size_t)(sr0 + 16) * F_LD + nt * 16, s1,
                                        F_LD, wmma::mem_row_major);
            }
            __syncwarp();

            if (mask) {  // scalar mask + exp on own 32-row strip
                const int row = sr0 + l;           // lane -> row, all 64 cols
                float* Srow = Ps + (size_t)row * F_LD;
                const int qg = qt * 128 + row;
                const int jg0 = kt * 64;
#pragma unroll
                for (int i = 0; i < 16; ++i) {
                    float4 v = *(float4*)(Srow + i * 4);
                    int j = jg0 + i * 4;
                    v.x = (j + 0 > qg) ? 0.f : __expf(v.x);
                    v.y = (j + 1 > qg) ? 0.f : __expf(v.y);
                    v.z = (j + 2 > qg) ? 0.f : __expf(v.z);
                    v.w = (j + 3 > qg) ? 0.f : __expf(v.w);
                    *(float4*)(Srow + i * 4) = v;
                }
                __syncwarp();
            }

            // ---- O strips += P @ V ; l strips += P @ ones (V resident) ----
#pragma unroll
            for (int ks = 0; ks < 8; ++ks) {
                wmma::fragment<wmma::matrix_a, 16, 16, 8, wmma::precision::tf32,
                               wmma::row_major> pa0, pa1;
                wmma::load_matrix_sync(pa0, Ps + (size_t)sr0 * F_LD + ks * 8, F_LD);
                wmma::load_matrix_sync(pa1, Ps + (size_t)(sr0 + 16) * F_LD + ks * 8,
                                       F_LD);
#pragma unroll
                for (int nt = 0; nt < 4; ++nt) {
                    wmma::fragment<wmma::matrix_b, 16, 16, 8, wmma::precision::tf32,
                                   wmma::row_major> vb;
                    wmma::load_matrix_sync(vb, Vs + (size_t)(ks * 8) * F_LD + nt * 16,
                                           F_LD);
                    wmma::mma_sync(oacc[0][nt], pa0, vb, oacc[0][nt]);
                    wmma::mma_sync(oacc[1][nt], pa1, vb, oacc[1][nt]);
                }
                wmma::mma_sync(lacc[0], pa0, b_ones, lacc[0]);
                wmma::mma_sync(lacc[1], pa1, b_ones, lacc[1]);
            }
        }
        __syncthreads();   // all warps done with buffers (kt) before reuse
    }

    // ---- epilogue: O / l -> fp16 ctx (Ls aliases dead K0 buffer) ----
#pragma unroll
    for (int s2 = 0; s2 < 2; ++s2) {
#pragma unroll
        for (int nt = 0; nt < 4; ++nt)
            wmma::store_matrix_sync(Ps + (size_t)(sr0 + s2 * 16) * F_LD + nt * 16,
                                    oacc[s2][nt], F_LD, wmma::mem_row_major);
        wmma::store_matrix_sync(Ls + (size_t)w * 512 + s2 * 256, lacc[s2], 16,
                                wmma::mem_row_major);
    }
    __syncthreads();

    {
        const int row = tid;   // 128 rows, one per thread
        const float inv =
            1.f / Ls[(size_t)(row >> 5) * 512 + ((row >> 4) & 1) * 256 + (row & 15) * 16];
        __half* Og = O + (size_t)(b * TT + qt * 128 + row) * D_MODEL + headoff;
        const float* Sr = Ps + (size_t)row * F_LD;
#pragma unroll
        for (int i = 0; i < 8; ++i) {
            float4 v = *(const float4*)(Sr + i * 8);
            float4 v2 = *(const float4*)(Sr + i * 8 + 4);
            __half2 h0 = __floats2half2_rn(v.x * inv, v.y * inv);
            __half2 h1 = __floats2half2_rn(v.z * inv, v.w * inv);
            __half2 h2 = __floats2half2_rn(v2.x * inv, v2.y * inv);
            __half2 h3 = __floats2half2_rn(v2.z * inv, v2.w * inv);
            uint4 o;
            o.x = *(uint32_t*)&h0; o.y = *(uint32_t*)&h1;
            o.z = *(uint32_t*)&h2; o.w = *(uint32_t*)&h3;
            *(uint4*)(Og + i * 8) = o;
        }
    }
}

// ---------------------------------------------------------------------------
extern "C" void kernel_launch(void* const* d_in, const int* in_sizes, int n_in,
                              void* d_out, int out_size) {
    const float* x = (const float*)d_in[0];
    const float* Wq = (const float*)d_in[1];
    const float* Wk = (const float*)d_in[2];
    const float* Wv = (const float*)d_in[3];
    const float* Wo = (const float*)d_in[4];
    const float* bo = (const float*)d_in[5];
    float* out = (float*)d_out;

    __half *dXh, *dWh, *dChh;
    float *dQ, *dK, *dV;
    cudaGetSymbolAddress((void**)&dXh, g_Xh);
    cudaGetSymbolAddress((void**)&dWh, g_Wh);
    cudaGetSymbolAddress((void**)&dChh, g_Chh);
    cudaGetSymbolAddress((void**)&dQ, g_Q);
    cudaGetSymbolAddress((void**)&dK, g_K);
    cudaGetSymbolAddress((void**)&dV, g_V);
    __half* dWqh = dWh;
    __half* dWkh = dWh + (size_t)D_MODEL * D_MODEL;
    __half* dWvh = dWh + 2 * (size_t)D_MODEL * D_MODEL;
    __half* dWoh = dWh + 3 * (size_t)D_MODEL * D_MODEL;

    cudaFuncSetAttribute(gemm_qkv, cudaFuncAttributeMaxDynamicSharedMemorySize,
                         G_SMEM_BYTES);
    cudaFuncSetAttribute(gemm_o, cudaFuncAttributeMaxDynamicSharedMemorySize,
                         G_SMEM_BYTES);
    cudaFuncSetAttribute(flash_t, cudaFuncAttributeMaxDynamicSharedMemorySize,
                         F_SMEM_BYTES);

    const int nx4 = BT * D_MODEL / 4;
    const int nw4 = D_MODEL * D_MODEL / 4;
    conv_f2h<<<(nx4 + 255) / 256, 256>>>((const float4*)x, (uint2*)dXh, nx4);
    dim3 w4_grid((nw4 + 255) / 256, 4);
    conv_w4<<<w4_grid, 256>>>((const float4*)Wq, (const float4*)Wk,
                              (const float4*)Wv, (const float4*)Wo,
                              (uint2*)dWh, nw4);

    // fused QKV projection: one launch, 24x64 CTAs
    dim3 qkv_grid(3 * (D_MODEL / BN), BT / BM);  // (24, 64)
    gemm_qkv<<<qkv_grid, 256, G_SMEM_BYTES>>>(dXh, dWqh, dWkh, dWvh, dQ, dK, dV);

    // flash: heavy q-tiles scheduled first (qt reversed on slow axis)
    dim3 attn_grid(BB * N_HEADS, TT / 128);  // (64, 16)
    flash_t<<<attn_grid, 128, F_SMEM_BYTES>>>(dQ, dK, dV, dChh);

    dim3 gemm_grid(D_MODEL / BN, BT / BM);  // (8, 64)
    gemm_o<<<gemm_grid, 256, G_SMEM_BYTES>>>(dChh, dWoh, out, bo);
}

// round 16
// speedup vs baseline: 2.1634x; 1.8618x over previous
#include <cuda_runtime.h>
#include <cuda_fp16.h>
#include <mma.h>
#include <cstdint>

using namespace nvcuda;

#define D_MODEL 1024
#define N_HEADS 16
#define HEAD_DIM 64
#define BB 4
#define TT 2048
#define BT (BB * TT)  // 8192

// ---------------- scratch (__device__ globals; no allocs allowed) ----------
__device__ __half g_Xh[(size_t)BT * D_MODEL];
__device__ __half g_Wh[4][(size_t)D_MODEL * D_MODEL];
__device__ __half g_Qh[(size_t)BT * D_MODEL];
__device__ __half g_Kh[(size_t)BT * D_MODEL];
__device__ __half g_Vh[(size_t)BT * D_MODEL];
__device__ __half g_Chh[(size_t)BT * D_MODEL];

// ---------------- helpers ---------------------------------------------------
__device__ __forceinline__ uint32_t smem_u32(const void* p) {
    uint32_t a;
    asm("{ .reg .u64 t; cvta.to.shared.u64 t, %1; cvt.u32.u64 %0, t; }"
        : "=r"(a) : "l"(p));
    return a;
}
#define CP_ASYNC16(dst, src) \
    asm volatile("cp.async.cg.shared.global [%0], [%1], 16;" :: "r"(dst), "l"(src) : "memory")
#define CP_ASYNC_COMMIT() asm volatile("cp.async.commit_group;" ::: "memory")
#define CP_ASYNC_WAIT0() asm volatile("cp.async.wait_group 0;" ::: "memory")
#define CP_ASYNC_WAIT1() asm volatile("cp.async.wait_group 1;" ::: "memory")

// ---------------- fp32 -> fp16 pre-converts ---------------------------------
__global__ __launch_bounds__(256) void conv_f2h(const float4* __restrict__ in,
                                                uint2* __restrict__ out, int n4) {
    int i = blockIdx.x * 256 + threadIdx.x;
    if (i < n4) {
        float4 v = in[i];
        __half2 a = __floats2half2_rn(v.x, v.y);
        __half2 b = __floats2half2_rn(v.z, v.w);
        uint2 o;
        o.x = *(uint32_t*)&a;
        o.y = *(uint32_t*)&b;
        out[i] = o;
    }
}

__global__ __launch_bounds__(256) void conv_w4(const float4* __restrict__ w0,
                                               const float4* __restrict__ w1,
                                               const float4* __restrict__ w2,
                                               const float4* __restrict__ w3,
                                               uint2* __restrict__ outbase, int n4) {
    const float4* in = (blockIdx.y == 0) ? w0 : (blockIdx.y == 1) ? w1
                       : (blockIdx.y == 2) ? w2 : w3;
    uint2* out = outbase + (size_t)blockIdx.y * n4;
    int i = blockIdx.x * 256 + threadIdx.x;
    if (i < n4) {
        float4 v = in[i];
        __half2 a = __floats2half2_rn(v.x, v.y);
        __half2 b = __floats2half2_rn(v.z, v.w);
        uint2 o;
        o.x = *(uint32_t*)&a;
        o.y = *(uint32_t*)&b;
        out[i] = o;
    }
}

// ---------------------------------------------------------------------------
// fp16 WMMA GEMM core (proven datapath). MODE 0: fp32 out + bias.
// MODE 1: fp16 out (QKV path).
// ---------------------------------------------------------------------------
#define BM 128
#define BN 128
#define BK 64
#define A_LDH 72
#define B_LDH 136
#define C_LDF 136
#define A_BYTES (BM * A_LDH * 2)
#define B_BYTES (BK * B_LDH * 2)
#define BUF_BYTES (A_BYTES + B_BYTES)
#define G_SMEM_BYTES (2 * BUF_BYTES)
#define G_NCHUNK (D_MODEL / BK)

template <int MODE>
__device__ __forceinline__ void gemm_body(const __half* __restrict__ A,
                                          const __half* __restrict__ Bm,
                                          void* __restrict__ C,
                                          const float* __restrict__ bias,
                                          int bm, int bn, float* sm) {
    const int tid = threadIdx.x;
    const int wid = tid >> 5;
    const int warp_m = wid >> 1;
    const int warp_n = wid & 1;
    const uint32_t sbase = smem_u32(sm);

    wmma::fragment<wmma::accumulator, 16, 16, 16, float> acc[2][4];
#pragma unroll
    for (int i = 0; i < 2; ++i)
#pragma unroll
        for (int j = 0; j < 4; ++j) wmma::fill_fragment(acc[i][j], 0.f);

    const __half* Ab = A + (size_t)bm * D_MODEL;
    const __half* Bb = Bm + bn;

    auto issue = [&](int c) {
        const uint32_t buf = sbase + (uint32_t)(c & 1) * BUF_BYTES;
        const __half* Ag = Ab + c * BK;
        const __half* Bg = Bb + (size_t)(c * BK) * D_MODEL;
#pragma unroll
        for (int i = 0; i < 4; ++i) {
            int idx = i * 256 + tid;
            int row = idx >> 3, seg = idx & 7;
            CP_ASYNC16(buf + (uint32_t)(row * A_LDH + seg * 8) * 2,
                       Ag + (size_t)row * D_MODEL + seg * 8);
        }
#pragma unroll
        for (int i = 0; i < 4; ++i) {
            int idx = i * 256 + tid;
            int row = idx >> 4, seg = idx & 15;
            CP_ASYNC16(buf + A_BYTES + (uint32_t)(row * B_LDH + seg * 8) * 2,
                       Bg + (size_t)row * D_MODEL + seg * 8);
        }
        CP_ASYNC_COMMIT();
    };

    issue(0);
    for (int c = 0; c < G_NCHUNK; ++c) {
        if (c + 1 < G_NCHUNK) {
            issue(c + 1);
            CP_ASYNC_WAIT1();
        } else {
            CP_ASYNC_WAIT0();
        }
        __syncthreads();

        const __half* As = (const __half*)((const char*)sm + (size_t)(c & 1) * BUF_BYTES);
        const __half* Bs = As + A_BYTES / 2;

#pragma unroll
        for (int ks = 0; ks < BK / 16; ++ks) {
            wmma::fragment<wmma::matrix_a, 16, 16, 16, __half, wmma::row_major> a[2];
            wmma::fragment<wmma::matrix_b, 16, 16, 16, __half, wmma::row_major> b[4];
#pragma unroll
            for (int i = 0; i < 2; ++i)
                wmma::load_matrix_sync(
                    a[i], As + (size_t)(warp_m * 32 + i * 16) * A_LDH + ks * 16, A_LDH);
#pragma unroll
            for (int j = 0; j < 4; ++j)
                wmma::load_matrix_sync(
                    b[j], Bs + (size_t)(ks * 16) * B_LDH + warp_n * 64 + j * 16, B_LDH);
#pragma unroll
            for (int i = 0; i < 2; ++i)
#pragma unroll
                for (int j = 0; j < 4; ++j)
                    wmma::mma_sync(acc[i][j], a[i], b[j], acc[i][j]);
        }
        __syncthreads();
    }

    float* Cs = sm;
#pragma unroll
    for (int i = 0; i < 2; ++i)
#pragma unroll
        for (int j = 0; j < 4; ++j)
            wmma::store_matrix_sync(
                Cs + (size_t)(warp_m * 32 + i * 16) * C_LDF + warp_n * 64 + j * 16,
                acc[i][j], C_LDF, wmma::mem_row_major);
    __syncthreads();

#pragma unroll
    for (int i = 0; i < 16; ++i) {
        int idx = i * 256 + tid;
        int row = idx >> 5, c4 = (idx & 31) * 4;
        float4 v = *(const float4*)(Cs + (size_t)row * C_LDF + c4);
        if (MODE == 1) {
            __half2 h0 = __floats2half2_rn(v.x, v.y);
            __half2 h1 = __floats2half2_rn(v.z, v.w);
            uint2 o;
            o.x = *(uint32_t*)&h0;
            o.y = *(uint32_t*)&h1;
            *(uint2*)((__half*)C + (size_t)(bm + row) * D_MODEL + bn + c4) = o;
        } else {
            v.x += bias[bn + c4 + 0];
            v.y += bias[bn + c4 + 1];
            v.z += bias[bn + c4 + 2];
            v.w += bias[bn + c4 + 3];
            *(float4*)((float*)C + (size_t)(bm + row) * D_MODEL + bn + c4) = v;
        }
    }
}

// fused Q/K/V projection (fp16 outputs)
__global__ __launch_bounds__(256) void gemm_qkv(const __half* __restrict__ A,
                                                const __half* __restrict__ W0,
                                                const __half* __restrict__ W1,
                                                const __half* __restrict__ W2,
                                                __half* __restrict__ C0,
                                                __half* __restrict__ C1,
                                                __half* __restrict__ C2) {
    extern __shared__ float sm[];
    const int which = blockIdx.x >> 3;
    const int bn = (blockIdx.x & 7) * BN;
    const int bm = blockIdx.y * BM;
    const __half* Bm = (which == 0) ? W0 : (which == 1) ? W1 : W2;
    __half* C = (which == 0) ? C0 : (which == 1) ? C1 : C2;
    gemm_body<1>(A, Bm, C, nullptr, bm, bn, sm);
}

// O projection (+bias, fp32 out)
__global__ __launch_bounds__(256) void gemm_o(const __half* __restrict__ A,
                                              const __half* __restrict__ Bm,
                                              float* __restrict__ C,
                                              const float* __restrict__ bias) {
    extern __shared__ float sm[];
    gemm_body<0>(A, Bm, C, bias, blockIdx.y * BM, blockIdx.x * BN, sm);
}

// ---------------------------------------------------------------------------
// fp16 WMMA flash attention (causal) — R12 skeleton, fp16 datapath.
// 128 threads, 4 warps x 32-row strips, 128-row q tile.
// K0/K1+V0/V1 fp16 double buffers, ONE commit group per tile (tile top),
// 2 syncthreads/tile, qt reversed (heavy first).
// S computed in fp32 (m16n16k16, fp32 accum) -> scalar exp+mask+cvt pass
// writes fp16 P -> PV and l (P @ ones) in fp16 MMA, fp32 accum.
// K/V loader covers ALL 64 rows: 4 x 128 vectors (R7's bug was 2).
// ---------------------------------------------------------------------------
#define FH_LD 72                             // halves per K/V/P row
#define F_LD 68                              // floats per S row
#define KVH_BYTES (64 * FH_LD * 2)           // 9216
#define OFF_K0 0                             // two K buffers (18432)
#define OFF_V0 (2 * KVH_BYTES)               // 18432, two V buffers (->36864)
#define OFF_PS (4 * KVH_BYTES)               // 36864: fp32 S/O staging 128xF_LD
#define OFF_PH (OFF_PS + 128 * F_LD * 4)     // 71680: fp16 P 128xFH_LD
#define OFF_ONE (OFF_PH + 128 * FH_LD * 2)   // 90112: fp16 ones 16x16
#define F_SMEM_BYTES (OFF_ONE + 512)         // 90624 (88.5KB) -> 2 CTAs/SM

__global__ __launch_bounds__(128) void flash_h(const __half* __restrict__ Q,
                                               const __half* __restrict__ K,
                                               const __half* __restrict__ V,
                                               __half* __restrict__ O) {
    extern __shared__ char smb[];
    float* Ps = (float*)(smb + OFF_PS);
    __half* Ph = (__half*)(smb + OFF_PH);
    __half* Ones = (__half*)(smb + OFF_ONE);
    float* Ls = (float*)(smb + OFF_K0);   // aliased onto K0 (epilogue only)

    const int tid = threadIdx.x;
    const int w = tid >> 5;
    const int l = tid & 31;
    const int qt = (int)(gridDim.y - 1 - blockIdx.y);  // heavy tiles first
    const int bh = blockIdx.x;
    const int b = bh >> 4;
    const int h = bh & 15;

    const size_t headoff = (size_t)h * HEAD_DIM;
    const uint32_t sbase = smem_u32(smb);
    const int sr0 = w * 32;      // warp strip base row

    // ---- stage Q*0.125 (exact pow2 scale in fp16) into Ph + ones ----
    {
        const __half* Qg = Q + (size_t)(b * TT + qt * 128) * D_MODEL + headoff;
        const __half2 s2 = __floats2half2_rn(0.125f, 0.125f);
        for (int idx = tid; idx < 128 * 8; idx += 128) {
            int row = idx >> 3, seg = idx & 7;
            uint4 v = *(const uint4*)(Qg + (size_t)row * D_MODEL + seg * 8);
            __half2* hp = (__half2*)&v;
            hp[0] = __hmul2(hp[0], s2);
            hp[1] = __hmul2(hp[1], s2);
            hp[2] = __hmul2(hp[2], s2);
            hp[3] = __hmul2(hp[3], s2);
            *(uint4*)(Ph + (size_t)row * FH_LD + seg * 8) = v;
        }
        Ones[tid] = __float2half(1.0f);
        Ones[tid + 128] = __float2half(1.0f);
    }
    __syncthreads();

    wmma::fragment<wmma::matrix_a, 16, 16, 16, __half, wmma::row_major> qa[2][4];
#pragma unroll
    for (int s2i = 0; s2i < 2; ++s2i)
#pragma unroll
        for (int ks = 0; ks < 4; ++ks)
            wmma::load_matrix_sync(qa[s2i][ks],
                                   Ph + (size_t)(sr0 + s2i * 16) * FH_LD + ks * 16,
                                   FH_LD);

    wmma::fragment<wmma::matrix_b, 16, 16, 16, __half, wmma::row_major> b_ones;
    wmma::load_matrix_sync(b_ones, Ones, 16);

    wmma::fragment<wmma::accumulator, 16, 16, 16, float> oacc[2][4], lacc[2];
#pragma unroll
    for (int s2i = 0; s2i < 2; ++s2i) {
#pragma unroll
        for (int n = 0; n < 4; ++n) wmma::fill_fragment(oacc[s2i][n], 0.f);
        wmma::fill_fragment(lacc[s2i], 0.f);
    }
    __syncthreads();  // qa fragments read before P overwrites Ph

    const __half* Kb = K + (size_t)(b * TT) * D_MODEL + headoff;
    const __half* Vb = V + (size_t)(b * TT) * D_MODEL + headoff;

    // combined K+V tile load, ONE commit group.
    // 64 rows x 8 segs (16B) = 512 vectors each; 128 threads -> 4 iters. (FIX)
    auto issueKV = [&](int t) {
        const uint32_t kbuf = sbase + OFF_K0 + (uint32_t)(t & 1) * KVH_BYTES;
        const uint32_t vbuf = sbase + OFF_V0 + (uint32_t)(t & 1) * KVH_BYTES;
        const __half* Kg = Kb + (size_t)(t * 64) * D_MODEL;
        const __half* Vg = Vb + (size_t)(t * 64) * D_MODEL;
#pragma unroll
        for (int i = 0; i < 4; ++i) {
            int idx = i * 128 + tid;
            int row = idx >> 3, seg = idx & 7;
            uint32_t off = (uint32_t)(row * FH_LD + seg * 8) * 2;
            CP_ASYNC16(kbuf + off, Kg + (size_t)row * D_MODEL + seg * 8);
            CP_ASYNC16(vbuf + off, Vg + (size_t)row * D_MODEL + seg * 8);
        }
        CP_ASYNC_COMMIT();
    };

    issueKV(0);

    const int nkt = 2 * qt + 2;

    for (int kt = 0; kt < nkt; ++kt) {
        CP_ASYNC_WAIT0();
        __syncthreads();    // K(kt), V(kt) visible to all warps

        if (kt + 1 < nkt) issueKV(kt + 1);  // overlaps this whole tile

        const bool skip = (kt == 2 * qt + 1) && (w < 2);
        const bool mask = ((kt == 2 * qt) && (w < 2)) ||
                          ((kt == 2 * qt + 1) && (w >= 2));

        const __half* Ks = (const __half*)(smb + OFF_K0 + (size_t)(kt & 1) * KVH_BYTES);
        const __half* Vs = (const __half*)(smb + OFF_V0 + (size_t)(kt & 1) * KVH_BYTES);

        if (!skip) {
            // ---- S strips = Qstrips @ K^T (fp16 MMA, fp32 acc) ----
#pragma unroll
            for (int nt = 0; nt < 4; ++nt) {
                wmma::fragment<wmma::accumulator, 16, 16, 16, float> s0, s1;
                wmma::fill_fragment(s0, 0.f);
                wmma::fill_fragment(s1, 0.f);
#pragma unroll
                for (int ks = 0; ks < 4; ++ks) {
                    wmma::fragment<wmma::matrix_b, 16, 16, 16, __half,
                                   wmma::col_major> bf;
                    wmma::load_matrix_sync(bf, Ks + (size_t)(nt * 16) * FH_LD + ks * 16,
                                           FH_LD);
                    wmma::mma_sync(s0, qa[0][ks], bf, s0);
                    wmma::mma_sync(s1, qa[1][ks], bf, s1);
                }
                wmma::store_matrix_sync(Ps + (size_t)sr0 * F_LD + nt * 16, s0, F_LD,
                                        wmma::mem_row_major);
                wmma::store_matrix_sync(Ps + (size_t)(sr0 + 16) * F_LD + nt * 16, s1,
                                        F_LD, wmma::mem_row_major);
            }
            __syncwarp();

            // ---- scalar pass: exp (+ mask) + fp16 convert, own 32-row strip
            {
                const int row = sr0 + l;             // one row per lane, 64 cols
                const float* Srow = Ps + (size_t)row * F_LD;
                __half* Prow = Ph + (size_t)row * FH_LD;
                if (!mask) {
#pragma unroll
                    for (int i = 0; i < 16; ++i) {
                        float4 v = *(const float4*)(Srow + i * 4);
                        v.x = __expf(v.x); v.y = __expf(v.y);
                        v.z = __expf(v.z); v.w = __expf(v.w);
                        __half2 h0 = __floats2half2_rn(v.x, v.y);
                        __half2 h1 = __floats2half2_rn(v.z, v.w);
                        uint2 o; o.x = *(uint32_t*)&h0; o.y = *(uint32_t*)&h1;
                        *(uint2*)(Prow + i * 4) = o;
                    }
                } else {
                    const int qg = qt * 128 + row;
                    const int jg0 = kt * 64;
#pragma unroll
                    for (int i = 0; i < 16; ++i) {
                        float4 v = *(const float4*)(Srow + i * 4);
                        int j = jg0 + i * 4;
                        v.x = (j + 0 > qg) ? 0.f : __expf(v.x);
                        v.y = (j + 1 > qg) ? 0.f : __expf(v.y);
                        v.z = (j + 2 > qg) ? 0.f : __expf(v.z);
                        v.w = (j + 3 > qg) ? 0.f : __expf(v.w);
                        __half2 h0 = __floats2half2_rn(v.x, v.y);
                        __half2 h1 = __floats2half2_rn(v.z, v.w);
                        uint2 o; o.x = *(uint32_t*)&h0; o.y = *(uint32_t*)&h1;
                        *(uint2*)(Prow + i * 4) = o;
                    }
                }
            }
            __syncwarp();

            // ---- O strips += P @ V ; l strips += P @ ones ----
#pragma unroll
            for (int ks = 0; ks < 4; ++ks) {
                wmma::fragment<wmma::matrix_a, 16, 16, 16, __half,
                               wmma::row_major> pa0, pa1;
                wmma::load_matrix_sync(pa0, Ph + (size_t)sr0 * FH_LD + ks * 16, FH_LD);
                wmma::load_matrix_sync(pa1, Ph + (size_t)(sr0 + 16) * FH_LD + ks * 16,
                                       FH_LD);
#pragma unroll
                for (int nt = 0; nt < 4; ++nt) {
                    wmma::fragment<wmma::matrix_b, 16, 16, 16, __half,
                                   wmma::row_major> vb;
                    wmma::load_matrix_sync(vb, Vs + (size_t)(ks * 16) * FH_LD + nt * 16,
                                           FH_LD);
                    wmma::mma_sync(oacc[0][nt], pa0, vb, oacc[0][nt]);
                    wmma::mma_sync(oacc[1][nt], pa1, vb, oacc[1][nt]);
                }
                wmma::mma_sync(lacc[0], pa0, b_ones, lacc[0]);
                wmma::mma_sync(lacc[1], pa1, b_ones, lacc[1]);
            }
        }
        __syncthreads();   // all warps done with buffers (kt) before reuse
    }

    // ---- epilogue: O / l -> fp16 ctx (Ls aliases dead K0 buffer) ----
#pragma unroll
    for (int s2i = 0; s2i < 2; ++s2i) {
#pragma unroll
        for (int nt = 0; nt < 4; ++nt)
            wmma::store_matrix_sync(Ps + (size_t)(sr0 + s2i * 16) * F_LD + nt * 16,
                                    oacc[s2i][nt], F_LD, wmma::mem_row_major);
        wmma::store_matrix_sync(Ls + (size_t)w * 512 + s2i * 256, lacc[s2i], 16,
                                wmma::mem_row_major);
    }
    __syncthreads();

    {
        const int row = tid;   // 128 rows, one per thread
        const float inv =
            1.f / Ls[(size_t)(row >> 5) * 512 + ((row >> 4) & 1) * 256 + (row & 15) * 16];
        __half* Og = O + (size_t)(b * TT + qt * 128 + row) * D_MODEL + headoff;
        const float* Sr = Ps + (size_t)row * F_LD;
#pragma unroll
        for (int i = 0; i < 8; ++i) {
            float4 v = *(const float4*)(Sr + i * 8);
            float4 v2 = *(const float4*)(Sr + i * 8 + 4);
            __half2 h0 = __floats2half2_rn(v.x * inv, v.y * inv);
            __half2 h1 = __floats2half2_rn(v.z * inv, v.w * inv);
            __half2 h2 = __floats2half2_rn(v2.x * inv, v2.y * inv);
            __half2 h3 = __floats2half2_rn(v2.z * inv, v2.w * inv);
            uint4 o;
            o.x = *(uint32_t*)&h0; o.y = *(uint32_t*)&h1;
            o.z = *(uint32_t*)&h2; o.w = *(uint32_t*)&h3;
            *(uint4*)(Og + i * 8) = o;
        }
    }
}

// ---------------------------------------------------------------------------
extern "C" void kernel_launch(void* const* d_in, const int* in_sizes, int n_in,
                              void* d_out, int out_size) {
    const float* x = (const float*)d_in[0];
    const float* Wq = (const float*)d_in[1];
    const float* Wk = (const float*)d_in[2];
    const float* Wv = (const float*)d_in[3];
    const float* Wo = (const float*)d_in[4];
    const float* bo = (const float*)d_in[5];
    float* out = (float*)d_out;

    __half *dXh, *dWh, *dQh, *dKh, *dVh, *dChh;
    cudaGetSymbolAddress((void**)&dXh, g_Xh);
    cudaGetSymbolAddress((void**)&dWh, g_Wh);
    cudaGetSymbolAddress((void**)&dQh, g_Qh);
    cudaGetSymbolAddress((void**)&dKh, g_Kh);
    cudaGetSymbolAddress((void**)&dVh, g_Vh);
    cudaGetSymbolAddress((void**)&dChh, g_Chh);
    __half* dWqh = dWh;
    __half* dWkh = dWh + (size_t)D_MODEL * D_MODEL;
    __half* dWvh = dWh + 2 * (size_t)D_MODEL * D_MODEL;
    __half* dWoh = dWh + 3 * (size_t)D_MODEL * D_MODEL;

    cudaFuncSetAttribute(gemm_qkv, cudaFuncAttributeMaxDynamicSharedMemorySize,
                         G_SMEM_BYTES);
    cudaFuncSetAttribute(gemm_o, cudaFuncAttributeMaxDynamicSharedMemorySize,
                         G_SMEM_BYTES);
    cudaFuncSetAttribute(flash_h, cudaFuncAttributeMaxDynamicSharedMemorySize,
                         F_SMEM_BYTES);

    const int nx4 = BT * D_MODEL / 4;
    const int nw4 = D_MODEL * D_MODEL / 4;
    conv_f2h<<<(nx4 + 255) / 256, 256>>>((const float4*)x, (uint2*)dXh, nx4);
    dim3 w4_grid((nw4 + 255) / 256, 4);
    conv_w4<<<w4_grid, 256>>>((const float4*)Wq, (const float4*)Wk,
                              (const float4*)Wv, (const float4*)Wo,
                              (uint2*)dWh, nw4);

    // fused QKV projection (fp16 outputs): one launch, 24x64 CTAs
    dim3 qkv_grid(3 * (D_MODEL / BN), BT / BM);  // (24, 64)
    gemm_qkv<<<qkv_grid, 256, G_SMEM_BYTES>>>(dXh, dWqh, dWkh, dWvh, dQh, dKh, dVh);

    // flash: heavy q-tiles scheduled first (qt reversed on slow axis)
    dim3 attn_grid(BB * N_HEADS, TT / 128);  // (64, 16)
    flash_h<<<attn_grid, 128, F_SMEM_BYTES>>>(dQh, dKh, dVh, dChh);

    dim3 gemm_grid(D_MODEL / BN, BT / BM);  // (8, 64)
    gemm_o<<<gemm_grid, 256, G_SMEM_BYTES>>>(dChh, dWoh, out, bo);
}

// round 17
// speedup vs baseline: 2.2766x; 1.0523x over previous
#include <cuda_runtime.h>
#include <cuda_fp16.h>
#include <mma.h>
#include <cstdint>

using namespace nvcuda;

#define D_MODEL 1024
#define N_HEADS 16
#define HEAD_DIM 64
#define BB 4
#define TT 2048
#define BT (BB * TT)  // 8192

// ---------------- scratch (__device__ globals; no allocs allowed) ----------
__device__ __half g_Xh[(size_t)BT * D_MODEL];
__device__ __half g_Wh[4][(size_t)D_MODEL * D_MODEL];
__device__ __half g_Qh[(size_t)BT * D_MODEL];
__device__ __half g_Kh[(size_t)BT * D_MODEL];
__device__ __half g_Vh[(size_t)BT * D_MODEL];
__device__ __half g_Chh[(size_t)BT * D_MODEL];

// ---------------- helpers ---------------------------------------------------
__device__ __forceinline__ uint32_t smem_u32(const void* p) {
    uint32_t a;
    asm("{ .reg .u64 t; cvta.to.shared.u64 t, %1; cvt.u32.u64 %0, t; }"
        : "=r"(a) : "l"(p));
    return a;
}
#define CP_ASYNC16(dst, src) \
    asm volatile("cp.async.cg.shared.global [%0], [%1], 16;" :: "r"(dst), "l"(src) : "memory")
#define CP_ASYNC_COMMIT() asm volatile("cp.async.commit_group;" ::: "memory")
#define CP_ASYNC_WAIT0() asm volatile("cp.async.wait_group 0;" ::: "memory")
#define CP_ASYNC_WAIT1() asm volatile("cp.async.wait_group 1;" ::: "memory")

// ---------------- fp32 -> fp16 pre-converts ---------------------------------
__global__ __launch_bounds__(256) void conv_f2h(const float4* __restrict__ in,
                                                uint2* __restrict__ out, int n4) {
    int i = blockIdx.x * 256 + threadIdx.x;
    if (i < n4) {
        float4 v = in[i];
        __half2 a = __floats2half2_rn(v.x, v.y);
        __half2 b = __floats2half2_rn(v.z, v.w);
        uint2 o;
        o.x = *(uint32_t*)&a;
        o.y = *(uint32_t*)&b;
        out[i] = o;
    }
}

__global__ __launch_bounds__(256) void conv_w4(const float4* __restrict__ w0,
                                               const float4* __restrict__ w1,
                                               const float4* __restrict__ w2,
                                               const float4* __restrict__ w3,
                                               uint2* __restrict__ outbase, int n4) {
    const float4* in = (blockIdx.y == 0) ? w0 : (blockIdx.y == 1) ? w1
                       : (blockIdx.y == 2) ? w2 : w3;
    uint2* out = outbase + (size_t)blockIdx.y * n4;
    int i = blockIdx.x * 256 + threadIdx.x;
    if (i < n4) {
        float4 v = in[i];
        __half2 a = __floats2half2_rn(v.x, v.y);
        __half2 b = __floats2half2_rn(v.z, v.w);
        uint2 o;
        o.x = *(uint32_t*)&a;
        o.y = *(uint32_t*)&b;
        out[i] = o;
    }
}

// ---------------------------------------------------------------------------
// fp16 WMMA GEMM — 128 threads, 4 warps (2x2), warp tile 64x64, CTA 128x128,
// BK=64. Load:MMA ratio 0.5 (8 frag loads -> 16 MMAs per ks step).
// MODE 0: fp32 out + bias.  MODE 1: fp16 out (QKV path).
// ---------------------------------------------------------------------------
#define BM 128
#define BN 128
#define BK 64
#define A_LDH 72
#define B_LDH 136
#define C_LDF 136
#define A_BYTES (BM * A_LDH * 2)            // 18432
#define B_BYTES (BK * B_LDH * 2)            // 17408
#define BUF_BYTES (A_BYTES + B_BYTES)       // 35840
#define G_SMEM_BYTES (2 * BUF_BYTES)        // 71680 (>= 128*136*4 epilogue)
#define G_NCHUNK (D_MODEL / BK)             // 16

template <int MODE>
__device__ __forceinline__ void gemm_body(const __half* __restrict__ A,
                                          const __half* __restrict__ Bm,
                                          void* __restrict__ C,
                                          const float* __restrict__ bias,
                                          int bm, int bn, float* sm) {
    const int tid = threadIdx.x;
    const int wid = tid >> 5;
    const int warp_m = wid >> 1;          // 0..1 (64-row strips)
    const int warp_n = wid & 1;           // 0..1 (64-col strips)
    const uint32_t sbase = smem_u32(sm);

    wmma::fragment<wmma::accumulator, 16, 16, 16, float> acc[4][4];
#pragma unroll
    for (int i = 0; i < 4; ++i)
#pragma unroll
        for (int j = 0; j < 4; ++j) wmma::fill_fragment(acc[i][j], 0.f);

    const __half* Ab = A + (size_t)bm * D_MODEL;
    const __half* Bb = Bm + bn;

    auto issue = [&](int c) {
        const uint32_t buf = sbase + (uint32_t)(c & 1) * BUF_BYTES;
        const __half* Ag = Ab + c * BK;
        const __half* Bg = Bb + (size_t)(c * BK) * D_MODEL;
        // A: 128 rows x 8 segs = 1024 vectors; 128 thr -> 8 iters
#pragma unroll
        for (int i = 0; i < 8; ++i) {
            int idx = i * 128 + tid;
            int row = idx >> 3, seg = idx & 7;
            CP_ASYNC16(buf + (uint32_t)(row * A_LDH + seg * 8) * 2,
                       Ag + (size_t)row * D_MODEL + seg * 8);
        }
        // B: 64 rows x 16 segs = 1024 vectors
#pragma unroll
        for (int i = 0; i < 8; ++i) {
            int idx = i * 128 + tid;
            int row = idx >> 4, seg = idx & 15;
            CP_ASYNC16(buf + A_BYTES + (uint32_t)(row * B_LDH + seg * 8) * 2,
                       Bg + (size_t)row * D_MODEL + seg * 8);
        }
        CP_ASYNC_COMMIT();
    };

    issue(0);
    for (int c = 0; c < G_NCHUNK; ++c) {
        if (c + 1 < G_NCHUNK) {
            issue(c + 1);
            CP_ASYNC_WAIT1();
        } else {
            CP_ASYNC_WAIT0();
        }
        __syncthreads();

        const __half* As = (const __half*)((const char*)sm + (size_t)(c & 1) * BUF_BYTES);
        const __half* Bs = As + A_BYTES / 2;

#pragma unroll
        for (int ks = 0; ks < BK / 16; ++ks) {
            wmma::fragment<wmma::matrix_a, 16, 16, 16, __half, wmma::row_major> a[4];
            wmma::fragment<wmma::matrix_b, 16, 16, 16, __half, wmma::row_major> b[4];
#pragma unroll
            for (int i = 0; i < 4; ++i)
                wmma::load_matrix_sync(
                    a[i], As + (size_t)(warp_m * 64 + i * 16) * A_LDH + ks * 16, A_LDH);
#pragma unroll
            for (int j = 0; j < 4; ++j)
                wmma::load_matrix_sync(
                    b[j], Bs + (size_t)(ks * 16) * B_LDH + warp_n * 64 + j * 16, B_LDH);
#pragma unroll
            for (int i = 0; i < 4; ++i)
#pragma unroll
                for (int j = 0; j < 4; ++j)
                    wmma::mma_sync(acc[i][j], a[i], b[j], acc[i][j]);
        }
        __syncthreads();
    }

    float* Cs = sm;
#pragma unroll
    for (int i = 0; i < 4; ++i)
#pragma unroll
        for (int j = 0; j < 4; ++j)
            wmma::store_matrix_sync(
                Cs + (size_t)(warp_m * 64 + i * 16) * C_LDF + warp_n * 64 + j * 16,
                acc[i][j], C_LDF, wmma::mem_row_major);
    __syncthreads();

#pragma unroll
    for (int i = 0; i < 32; ++i) {
        int idx = i * 128 + tid;
        int row = idx >> 5, c4 = (idx & 31) * 4;
        float4 v = *(const float4*)(Cs + (size_t)row * C_LDF + c4);
        if (MODE == 1) {
            __half2 h0 = __floats2half2_rn(v.x, v.y);
            __half2 h1 = __floats2half2_rn(v.z, v.w);
            uint2 o;
            o.x = *(uint32_t*)&h0;
            o.y = *(uint32_t*)&h1;
            *(uint2*)((__half*)C + (size_t)(bm + row) * D_MODEL + bn + c4) = o;
        } else {
            v.x += bias[bn + c4 + 0];
            v.y += bias[bn + c4 + 1];
            v.z += bias[bn + c4 + 2];
            v.w += bias[bn + c4 + 3];
            *(float4*)((float*)C + (size_t)(bm + row) * D_MODEL + bn + c4) = v;
        }
    }
}

// fused Q/K/V projection (fp16 outputs)
__global__ __launch_bounds__(128) void gemm_qkv(const __half* __restrict__ A,
                                                const __half* __restrict__ W0,
                                                const __half* __restrict__ W1,
                                                const __half* __restrict__ W2,
                                                __half* __restrict__ C0,
                                                __half* __restrict__ C1,
                                                __half* __restrict__ C2) {
    extern __shared__ float sm[];
    const int which = blockIdx.x >> 3;
    const int bn = (blockIdx.x & 7) * BN;
    const int bm = blockIdx.y * BM;
    const __half* Bm = (which == 0) ? W0 : (which == 1) ? W1 : W2;
    __half* C = (which == 0) ? C0 : (which == 1) ? C1 : C2;
    gemm_body<1>(A, Bm, C, nullptr, bm, bn, sm);
}

// O projection (+bias, fp32 out)
__global__ __launch_bounds__(128) void gemm_o(const __half* __restrict__ A,
                                              const __half* __restrict__ Bm,
                                              float* __restrict__ C,
                                              const float* __restrict__ bias) {
    extern __shared__ float sm[];
    gemm_body<0>(A, Bm, C, bias, blockIdx.y * BM, blockIdx.x * BN, sm);
}

// ---------------------------------------------------------------------------
// fp16 WMMA flash attention (causal) — R16 proven kernel with scalar row-sum
// l (each lane owns one full row in the exp pass -> register accumulation;
// P @ ones MMAs, Ones and Ls buffers deleted).
// 128 threads, 4 warps x 32-row strips, 128-row q tile, K/V fp16 double
// buffers, ONE commit group per tile, 2 syncs/tile, qt reversed.
// ---------------------------------------------------------------------------
#define FH_LD 72                             // halves per K/V/P row
#define F_LD 68                              // floats per S row
#define KVH_BYTES (64 * FH_LD * 2)           // 9216
#define OFF_K0 0                             // two K buffers (18432)
#define OFF_V0 (2 * KVH_BYTES)               // two V buffers (->36864)
#define OFF_PS (4 * KVH_BYTES)               // 36864: fp32 S/O staging 128xF_LD
#define OFF_PH (OFF_PS + 128 * F_LD * 4)     // 71680: fp16 P 128xFH_LD
#define F_SMEM_BYTES (OFF_PH + 128 * FH_LD * 2)  // 90112 (88KB) -> 2 CTAs/SM

__global__ __launch_bounds__(128) void flash_h(const __half* __restrict__ Q,
                                               const __half* __restrict__ K,
                                               const __half* __restrict__ V,
                                               __half* __restrict__ O) {
    extern __shared__ char smb[];
    float* Ps = (float*)(smb + OFF_PS);
    __half* Ph = (__half*)(smb + OFF_PH);

    const int tid = threadIdx.x;
    const int w = tid >> 5;
    const int l = tid & 31;
    const int qt = (int)(gridDim.y - 1 - blockIdx.y);  // heavy tiles first
    const int bh = blockIdx.x;
    const int b = bh >> 4;
    const int h = bh & 15;

    const size_t headoff = (size_t)h * HEAD_DIM;
    const uint32_t sbase = smem_u32(smb);
    const int sr0 = w * 32;      // warp strip base row

    // ---- stage Q*0.125 (exact pow2 scale in fp16) into Ph ----
    {
        const __half* Qg = Q + (size_t)(b * TT + qt * 128) * D_MODEL + headoff;
        const __half2 s2 = __floats2half2_rn(0.125f, 0.125f);
        for (int idx = tid; idx < 128 * 8; idx += 128) {
            int row = idx >> 3, seg = idx & 7;
            uint4 v = *(const uint4*)(Qg + (size_t)row * D_MODEL + seg * 8);
            __half2* hp = (__half2*)&v;
            hp[0] = __hmul2(hp[0], s2);
            hp[1] = __hmul2(hp[1], s2);
            hp[2] = __hmul2(hp[2], s2);
            hp[3] = __hmul2(hp[3], s2);
            *(uint4*)(Ph + (size_t)row * FH_LD + seg * 8) = v;
        }
    }
    __syncthreads();

    wmma::fragment<wmma::matrix_a, 16, 16, 16, __half, wmma::row_major> qa[2][4];
#pragma unroll
    for (int s2i = 0; s2i < 2; ++s2i)
#pragma unroll
        for (int ks = 0; ks < 4; ++ks)
            wmma::load_matrix_sync(qa[s2i][ks],
                                   Ph + (size_t)(sr0 + s2i * 16) * FH_LD + ks * 16,
                                   FH_LD);

    wmma::fragment<wmma::accumulator, 16, 16, 16, float> oacc[2][4];
#pragma unroll
    for (int s2i = 0; s2i < 2; ++s2i)
#pragma unroll
        for (int n = 0; n < 4; ++n) wmma::fill_fragment(oacc[s2i][n], 0.f);
    float l_acc = 0.f;            // row sum for row (sr0 + l) == tid
    __syncthreads();  // qa fragments read before P overwrites Ph

    const __half* Kb = K + (size_t)(b * TT) * D_MODEL + headoff;
    const __half* Vb = V + (size_t)(b * TT) * D_MODEL + headoff;

    // combined K+V tile load, ONE commit group.
    // 64 rows x 8 segs (16B) = 512 vectors each; 128 threads -> 4 iters.
    auto issueKV = [&](int t) {
        const uint32_t kbuf = sbase + OFF_K0 + (uint32_t)(t & 1) * KVH_BYTES;
        const uint32_t vbuf = sbase + OFF_V0 + (uint32_t)(t & 1) * KVH_BYTES;
        const __half* Kg = Kb + (size_t)(t * 64) * D_MODEL;
        const __half* Vg = Vb + (size_t)(t * 64) * D_MODEL;
#pragma unroll
        for (int i = 0; i < 4; ++i) {
            int idx = i * 128 + tid;
            int row = idx >> 3, seg = idx & 7;
            uint32_t off = (uint32_t)(row * FH_LD + seg * 8) * 2;
            CP_ASYNC16(kbuf + off, Kg + (size_t)row * D_MODEL + seg * 8);
            CP_ASYNC16(vbuf + off, Vg + (size_t)row * D_MODEL + seg * 8);
        }
        CP_ASYNC_COMMIT();
    };

    issueKV(0);

    const int nkt = 2 * qt + 2;

    for (int kt = 0; kt < nkt; ++kt) {
        CP_ASYNC_WAIT0();
        __syncthreads();    // K(kt), V(kt) visible to all warps

        if (kt + 1 < nkt) issueKV(kt + 1);  // overlaps this whole tile

        const bool skip = (kt == 2 * qt + 1) && (w < 2);
        const bool mask = ((kt == 2 * qt) && (w < 2)) ||
                          ((kt == 2 * qt + 1) && (w >= 2));

        const __half* Ks = (const __half*)(smb + OFF_K0 + (size_t)(kt & 1) * KVH_BYTES);
        const __half* Vs = (const __half*)(smb + OFF_V0 + (size_t)(kt & 1) * KVH_BYTES);

        if (!skip) {
            // ---- S strips = Qstrips @ K^T (fp16 MMA, fp32 acc) ----
#pragma unroll
            for (int nt = 0; nt < 4; ++nt) {
                wmma::fragment<wmma::accumulator, 16, 16, 16, float> s0, s1;
                wmma::fill_fragment(s0, 0.f);
                wmma::fill_fragment(s1, 0.f);
#pragma unroll
                for (int ks = 0; ks < 4; ++ks) {
                    wmma::fragment<wmma::matrix_b, 16, 16, 16, __half,
                                   wmma::col_major> bf;
                    wmma::load_matrix_sync(bf, Ks + (size_t)(nt * 16) * FH_LD + ks * 16,
                                           FH_LD);
                    wmma::mma_sync(s0, qa[0][ks], bf, s0);
                    wmma::mma_sync(s1, qa[1][ks], bf, s1);
                }
                wmma::store_matrix_sync(Ps + (size_t)sr0 * F_LD + nt * 16, s0, F_LD,
                                        wmma::mem_row_major);
                wmma::store_matrix_sync(Ps + (size_t)(sr0 + 16) * F_LD + nt * 16, s1,
                                        F_LD, wmma::mem_row_major);
            }
            __syncwarp();

            // ---- scalar pass: exp (+ mask) + fp16 convert + row sum ----
            {
                const int row = sr0 + l;             // one row per lane, 64 cols
                const float* Srow = Ps + (size_t)row * F_LD;
                __half* Prow = Ph + (size_t)row * FH_LD;
                float part = 0.f;
                if (!mask) {
#pragma unroll
                    for (int i = 0; i < 16; ++i) {
                        float4 v = *(const float4*)(Srow + i * 4);
                        v.x = __expf(v.x); v.y = __expf(v.y);
                        v.z = __expf(v.z); v.w = __expf(v.w);
                        part += v.x + v.y + v.z + v.w;
                        __half2 h0 = __floats2half2_rn(v.x, v.y);
                        __half2 h1 = __floats2half2_rn(v.z, v.w);
                        uint2 o; o.x = *(uint32_t*)&h0; o.y = *(uint32_t*)&h1;
                        *(uint2*)(Prow + i * 4) = o;
                    }
                } else {
                    const int qg = qt * 128 + row;
                    const int jg0 = kt * 64;
#pragma unroll
                    for (int i = 0; i < 16; ++i) {
                        float4 v = *(const float4*)(Srow + i * 4);
                        int j = jg0 + i * 4;
                        v.x = (j + 0 > qg) ? 0.f : __expf(v.x);
                        v.y = (j + 1 > qg) ? 0.f : __expf(v.y);
                        v.z = (j + 2 > qg) ? 0.f : __expf(v.z);
                        v.w = (j + 3 > qg) ? 0.f : __expf(v.w);
                        part += v.x + v.y + v.z + v.w;
                        __half2 h0 = __floats2half2_rn(v.x, v.y);
                        __half2 h1 = __floats2half2_rn(v.z, v.w);
                        uint2 o; o.x = *(uint32_t*)&h0; o.y = *(uint32_t*)&h1;
                        *(uint2*)(Prow + i * 4) = o;
                    }
                }
                l_acc += part;
            }
            __syncwarp();

            // ---- O strips += P @ V ----
#pragma unroll
            for (int ks = 0; ks < 4; ++ks) {
                wmma::fragment<wmma::matrix_a, 16, 16, 16, __half,
                               wmma::row_major> pa0, pa1;
                wmma::load_matrix_sync(pa0, Ph + (size_t)sr0 * FH_LD + ks * 16, FH_LD);
                wmma::load_matrix_sync(pa1, Ph + (size_t)(sr0 + 16) * FH_LD + ks * 16,
                                       FH_LD);
#pragma unroll
                for (int nt = 0; nt < 4; ++nt) {
                    wmma::fragment<wmma::matrix_b, 16, 16, 16, __half,
                                   wmma::row_major> vb;
                    wmma::load_matrix_sync(vb, Vs + (size_t)(ks * 16) * FH_LD + nt * 16,
                                           FH_LD);
                    wmma::mma_sync(oacc[0][nt], pa0, vb, oacc[0][nt]);
                    wmma::mma_sync(oacc[1][nt], pa1, vb, oacc[1][nt]);
                }
            }
        }
        __syncthreads();   // all warps done with buffers (kt) before reuse
    }

    // ---- epilogue: O / l -> fp16 ctx (thread tid owns row tid) ----
#pragma unroll
    for (int s2i = 0; s2i < 2; ++s2i)
#pragma unroll
        for (int nt = 0; nt < 4; ++nt)
            wmma::store_matrix_sync(Ps + (size_t)(sr0 + s2i * 16) * F_LD + nt * 16,
                                    oacc[s2i][nt], F_LD, wmma::mem_row_major);
    __syncthreads();

    {
        const int row = tid;   // 128 rows, one per thread (== sr0 + l)
        const float inv = 1.f / l_acc;
        __half* Og = O + (size_t)(b * TT + qt * 128 + row) * D_MODEL + headoff;
        const float* Sr = Ps + (size_t)row * F_LD;
#pragma unroll
        for (int i = 0; i < 8; ++i) {
            float4 v = *(const float4*)(Sr + i * 8);
            float4 v2 = *(const float4*)(Sr + i * 8 + 4);
            __half2 h0 = __floats2half2_rn(v.x * inv, v.y * inv);
            __half2 h1 = __floats2half2_rn(v.z * inv, v.w * inv);
            __half2 h2 = __floats2half2_rn(v2.x * inv, v2.y * inv);
            __half2 h3 = __floats2half2_rn(v2.z * inv, v2.w * inv);
            uint4 o;
            o.x = *(uint32_t*)&h0; o.y = *(uint32_t*)&h1;
            o.z = *(uint32_t*)&h2; o.w = *(uint32_t*)&h3;
            *(uint4*)(Og + i * 8) = o;
        }
    }
}

// ---------------------------------------------------------------------------
extern "C" void kernel_launch(void* const* d_in, const int* in_sizes, int n_in,
                              void* d_out, int out_size) {
    const float* x = (const float*)d_in[0];
    const float* Wq = (const float*)d_in[1];
    const float* Wk = (const float*)d_in[2];
    const float* Wv = (const float*)d_in[3];
    const float* Wo = (const float*)d_in[4];
    const float* bo = (const float*)d_in[5];
    float* out = (float*)d_out;

    __half *dXh, *dWh, *dQh, *dKh, *dVh, *dChh;
    cudaGetSymbolAddress((void**)&dXh, g_Xh);
    cudaGetSymbolAddress((void**)&dWh, g_Wh);
    cudaGetSymbolAddress((void**)&dQh, g_Qh);
    cudaGetSymbolAddress((void**)&dKh, g_Kh);
    cudaGetSymbolAddress((void**)&dVh, g_Vh);
    cudaGetSymbolAddress((void**)&dChh, g_Chh);
    __half* dWqh = dWh;
    __half* dWkh = dWh + (size_t)D_MODEL * D_MODEL;
    __half* dWvh = dWh + 2 * (size_t)D_MODEL * D_MODEL;
    __half* dWoh = dWh + 3 * (size_t)D_MODEL * D_MODEL;

    cudaFuncSetAttribute(gemm_qkv, cudaFuncAttributeMaxDynamicSharedMemorySize,
                         G_SMEM_BYTES);
    cudaFuncSetAttribute(gemm_o, cudaFuncAttributeMaxDynamicSharedMemorySize,
                         G_SMEM_BYTES);
    cudaFuncSetAttribute(flash_h, cudaFuncAttributeMaxDynamicSharedMemorySize,
                         F_SMEM_BYTES);

    const int nx4 = BT * D_MODEL / 4;
    const int nw4 = D_MODEL * D_MODEL / 4;
    conv_f2h<<<(nx4 + 255) / 256, 256>>>((const float4*)x, (uint2*)dXh, nx4);
    dim3 w4_grid((nw4 + 255) / 256, 4);
    conv_w4<<<w4_grid, 256>>>((const float4*)Wq, (const float4*)Wk,
                              (const float4*)Wv, (const float4*)Wo,
                              (uint2*)dWh, nw4);

    // fused QKV projection (fp16 outputs)
    dim3 qkv_grid(3 * (D_MODEL / BN), BT / BM);  // (24, 64)
    gemm_qkv<<<qkv_grid, 128, G_SMEM_BYTES>>>(dXh, dWqh, dWkh, dWvh, dQh, dKh, dVh);

    // flash: heavy q-tiles scheduled first (qt reversed on slow axis)
    dim3 attn_grid(BB * N_HEADS, TT / 128);  // (64, 16)
    flash_h<<<attn_grid, 128, F_SMEM_BYTES>>>(dQh, dKh, dVh, dChh);

    dim3 gemm_grid(D_MODEL / BN, BT / BM);  // (8, 64)
    gemm_o<<<gemm_grid, 128, G_SMEM_BYTES>>>(dChh, dWoh, out, bo);
}